// round 7
// baseline (speedup 1.0000x reference)
#include <cuda_runtime.h>
#include <cuda_bf16.h>
#include <math_constants.h>
#include <cstdint>

// Problem shape (fixed): B=16, T=2048, C=512, H=64
#define BATCH 16
#define SEQ   2048
#define CDIM  512
#define HDIM  64
#define END_TOKEN 32000

#define ROWS_TOTAL (BATCH * SEQ)          // 32768
#define SCALE 0.04419417382415922f        // 512^-0.5

__device__ __forceinline__ float tf32r(float x) {
    float y; asm("cvt.rna.tf32.f32 %0,%1;" : "=f"(y) : "f"(x)); return y;
}

// m16n8k8 tf32 mma (sm_80 portable feature -> fallback HMMA on sm_103)
__device__ __forceinline__ void mma_tf32(float* d, const uint32_t* a, const uint32_t* b) {
    asm volatile(
        "mma.sync.aligned.m16n8k8.row.col.f32.tf32.tf32.f32 "
        "{%0,%1,%2,%3}, {%4,%5,%6,%7}, {%8,%9}, {%0,%1,%2,%3};"
        : "+f"(d[0]), "+f"(d[1]), "+f"(d[2]), "+f"(d[3])
        : "r"(a[0]), "r"(a[1]), "r"(a[2]), "r"(a[3]), "r"(b[0]), "r"(b[1]));
}

// Scratch (allocation-free rule: __device__ globals)
__device__ float g_q[ROWS_TOTAL * HDIM];
__device__ float g_k[ROWS_TOTAL * HDIM];
__device__ float g_v[ROWS_TOTAL * HDIM];
__device__ float g_wt[3 * HDIM * CDIM];   // W^T, tf32-rounded: [mat][n][k]
__device__ int   g_limit[BATCH];

// ---------------------------------------------------------------------------
// Kernel 0: transpose W -> g_wt[m][n][k] (K-major) with tf32 rounding.
// ---------------------------------------------------------------------------
__global__ void transpose_w_kernel(const float* __restrict__ Wk,
                                   const float* __restrict__ Wq,
                                   const float* __restrict__ Wv)
{
    const int m  = blockIdx.x / 16;
    const int ks = blockIdx.x % 16;           // k-slice of 32
    const float* src = (m == 0) ? Wq : (m == 1) ? Wk : Wv;
    float* dst = g_wt + (size_t)m * HDIM * CDIM;
    for (int i = threadIdx.x; i < 32 * 64; i += 256) {
        int k = ks * 32 + (i >> 6);
        int n = i & 63;
        dst[(size_t)n * CDIM + k] = tf32r(src[(size_t)k * HDIM + n]);
    }
}

// ---------------------------------------------------------------------------
// Kernel 1: QKV projection via tf32 mma.sync.
// CTA tile: 128 rows x 96 cols (half of Q|K|V strip, selected by blockIdx.y).
// 8 warps = 4(M) x 2(N); warp tile 32 x 48. 2 CTAs/SM.
// ---------------------------------------------------------------------------
__global__ __launch_bounds__(256, 2) void proj_kernel(const float* __restrict__ x)
{
    __shared__ float As[128][36];
    __shared__ float Bs[96][36];

    const int t    = threadIdx.x;
    const int wid  = t >> 5;
    const int lane = t & 31;
    const int g    = lane >> 2;
    const int ctg  = lane & 3;
    const int wm   = wid >> 1;     // 0..3
    const int wn   = wid & 1;      // 0..1
    const int row0 = blockIdx.x * 128;
    const int col0 = blockIdx.y * 96;

    float acc[2][6][4];
#pragma unroll
    for (int mt = 0; mt < 2; mt++)
#pragma unroll
        for (int nt = 0; nt < 6; nt++)
#pragma unroll
            for (int i = 0; i < 4; i++) acc[mt][nt][i] = 0.f;

    for (int kc = 0; kc < 16; kc++) {
        // stage A: 128 rows x 32 cols, tf32-rounded. 2 threads/row x 16 cols.
        {
            int r = t >> 1, f = (t & 1) * 16;
            const float* xp = x + (size_t)(row0 + r) * CDIM + kc * 32 + f;
#pragma unroll
            for (int q4 = 0; q4 < 4; q4++) {
                float4 v = *reinterpret_cast<const float4*>(xp + q4 * 4);
                v.x = tf32r(v.x); v.y = tf32r(v.y);
                v.z = tf32r(v.z); v.w = tf32r(v.w);
                *reinterpret_cast<float4*>(&As[r][f + q4 * 4]) = v;
            }
        }
        // stage B: 96 rows x 32 cols (pre-rounded). 768 float4 tasks.
#pragma unroll
        for (int j = 0; j < 3; j++) {
            int id = t + 256 * j;
            int n  = id >> 3, f4 = (id & 7) * 4;
            float4 v = *reinterpret_cast<const float4*>(
                g_wt + (size_t)(col0 + n) * CDIM + kc * 32 + f4);
            *reinterpret_cast<float4*>(&Bs[n][f4]) = v;
        }
        __syncthreads();

#pragma unroll
        for (int ks = 0; ks < 4; ks++) {
            const int kb = ks * 8;
            uint32_t a[2][4];
#pragma unroll
            for (int mt = 0; mt < 2; mt++) {
                int row = wm * 32 + mt * 16;
                a[mt][0] = __float_as_uint(As[row + g][kb + ctg]);
                a[mt][1] = __float_as_uint(As[row + g + 8][kb + ctg]);
                a[mt][2] = __float_as_uint(As[row + g][kb + ctg + 4]);
                a[mt][3] = __float_as_uint(As[row + g + 8][kb + ctg + 4]);
            }
#pragma unroll
            for (int nt = 0; nt < 6; nt++) {
                int n = wn * 48 + nt * 8;
                uint32_t b[2];
                b[0] = __float_as_uint(Bs[n + g][kb + ctg]);
                b[1] = __float_as_uint(Bs[n + g][kb + ctg + 4]);
                mma_tf32(acc[0][nt], a[0], b);
                mma_tf32(acc[1][nt], a[1], b);
            }
        }
        __syncthreads();
    }

    // epilogue
    float* outp[3] = { g_q, g_k, g_v };
#pragma unroll
    for (int mt = 0; mt < 2; mt++) {
#pragma unroll
        for (int nt = 0; nt < 6; nt++) {
            int col = col0 + wn * 48 + nt * 8 + 2 * ctg;
            int mat = col >> 6, cc = col & 63;
            int r0 = row0 + wm * 32 + mt * 16 + g;
            *reinterpret_cast<float2*>(outp[mat] + (size_t)r0 * HDIM + cc) =
                make_float2(acc[mt][nt][0], acc[mt][nt][1]);
            *reinterpret_cast<float2*>(outp[mat] + (size_t)(r0 + 8) * HDIM + cc) =
                make_float2(acc[mt][nt][2], acc[mt][nt][3]);
        }
    }
}

// ---------------------------------------------------------------------------
// Kernel 2: end-token scan per batch (faithful; never fires for this dataset).
// ---------------------------------------------------------------------------
__global__ void limit_kernel(const int* __restrict__ idx)
{
    __shared__ int best;
    if (threadIdx.x == 0) best = SEQ;
    __syncthreads();
    const int b = blockIdx.x;
    for (int t = threadIdx.x; t < SEQ; t += blockDim.x)
        if (idx[(size_t)b * SEQ + t] == END_TOKEN) atomicMin(&best, t);
    __syncthreads();
    if (threadIdx.x == 0) g_limit[b] = best;
}

// ---------------------------------------------------------------------------
// Kernel 3: causal flash attention via tf32 mma.sync.
// Tile 128q x 128k. 8 warps, each owns 16 q-rows (full 128 k-cols for S).
// P never touches smem: S-fragment -> A-fragment via intra-quad shuffles.
// smem: Qs[128][68], Ks[128][68], VT[64][132] = 103,424 B -> 2 CTAs/SM.
// ---------------------------------------------------------------------------
#define QP 68
#define VP 132
#define OFF_KS (128 * QP)
#define OFF_VT (OFF_KS + 128 * QP)
#define ATTN_SMEM_FLOATS (OFF_VT + 64 * VP)
#define ATTN_SMEM_BYTES (ATTN_SMEM_FLOATS * 4)

__global__ __launch_bounds__(256, 2) void attn_kernel(float* __restrict__ out)
{
    extern __shared__ float smf[];
    float* Qs = smf;            // [128][QP]  [q][h]
    float* Ks = smf + OFF_KS;   // [128][QP]  [k][h]
    float* VT = smf + OFF_VT;   // [64][VP]   [h][k]

    const int t    = threadIdx.x;
    const int wid  = t >> 5;
    const int lane = t & 31;
    const int g    = lane >> 2;
    const int ctg  = lane & 3;
    const int qw   = wid * 16;              // warp's q-row base in tile
    const int b    = blockIdx.y;
    const int qt   = (gridDim.x - 1) - blockIdx.x;   // heavy tiles first
    const int q0   = qt * 128;

    // stage Q (tf32-rounded)
    {
        int r = t >> 1, f0 = (t & 1) * 32;
        const float* qp = g_q + ((size_t)b * SEQ + q0 + r) * HDIM + f0;
#pragma unroll
        for (int it = 0; it < 8; it++) {
            float4 v = *reinterpret_cast<const float4*>(qp + it * 4);
            v.x = tf32r(v.x); v.y = tf32r(v.y); v.z = tf32r(v.z); v.w = tf32r(v.w);
            *reinterpret_cast<float4*>(&Qs[r * QP + f0 + it * 4]) = v;
        }
    }

    float mrow[2] = { -CUDART_INF_F, -CUDART_INF_F };
    float lrow[2] = { 0.f, 0.f };
    float o[8][4];
#pragma unroll
    for (int nt = 0; nt < 8; nt++)
#pragma unroll
        for (int i = 0; i < 4; i++) o[nt][i] = 0.f;

    // shuffle-convert constants (intra-quad)
    const int qbase = lane & ~3;
    const int src0  = qbase + (ctg >> 1);
    const int src1  = src0 + 2;
    const bool codd = (ctg & 1);

    for (int kt = 0; kt <= qt; kt++) {
        __syncthreads();   // prior-iter smem reads done (also covers Q staging)

        // stage K [k][h] (rounded) and V transposed [h][k] (rounded)
        {
            int r = t >> 1, f0 = (t & 1) * 32;
            const size_t base = ((size_t)b * SEQ + kt * 128 + r) * HDIM + f0;
#pragma unroll
            for (int it = 0; it < 8; it++) {
                float4 kv = *reinterpret_cast<const float4*>(&g_k[base + it * 4]);
                kv.x = tf32r(kv.x); kv.y = tf32r(kv.y);
                kv.z = tf32r(kv.z); kv.w = tf32r(kv.w);
                *reinterpret_cast<float4*>(&Ks[r * QP + f0 + it * 4]) = kv;
                float4 vv = *reinterpret_cast<const float4*>(&g_v[base + it * 4]);
                int h = f0 + it * 4;
                VT[(h + 0) * VP + r] = tf32r(vv.x);
                VT[(h + 1) * VP + r] = tf32r(vv.y);
                VT[(h + 2) * VP + r] = tf32r(vv.z);
                VT[(h + 3) * VP + r] = tf32r(vv.w);
            }
        }
        __syncthreads();

        // ---- S = Q K^T : warp tile 16 x 128, 16 n-tiles ----
        float s[16][4];
#pragma unroll
        for (int nt = 0; nt < 16; nt++)
#pragma unroll
            for (int i = 0; i < 4; i++) s[nt][i] = 0.f;

#pragma unroll
        for (int ks = 0; ks < 8; ks++) {
            const int kb = ks * 8;
            uint32_t a[4];
            a[0] = __float_as_uint(Qs[(qw + g) * QP + kb + ctg]);
            a[1] = __float_as_uint(Qs[(qw + g + 8) * QP + kb + ctg]);
            a[2] = __float_as_uint(Qs[(qw + g) * QP + kb + ctg + 4]);
            a[3] = __float_as_uint(Qs[(qw + g + 8) * QP + kb + ctg + 4]);
#pragma unroll
            for (int nt = 0; nt < 16; nt++) {
                uint32_t bb[2];
                bb[0] = __float_as_uint(Ks[(nt * 8 + g) * QP + kb + ctg]);
                bb[1] = __float_as_uint(Ks[(nt * 8 + g) * QP + kb + ctg + 4]);
                mma_tf32(s[nt], a, bb);
            }
        }

        // ---- scale + causal mask + online softmax (rows g, g+8) ----
        const bool diag = (kt == qt);
        const int r0l = qw + g, r1l = r0l + 8;   // local q rows
        float rm0 = -CUDART_INF_F, rm1 = -CUDART_INF_F;
#pragma unroll
        for (int nt = 0; nt < 16; nt++) {
            int cl = nt * 8 + 2 * ctg;
#pragma unroll
            for (int c = 0; c < 2; c++) {
                float v0 = s[nt][c] * SCALE;
                float v1 = s[nt][2 + c] * SCALE;
                if (diag) {
                    if (cl + c > r0l) v0 = -1e30f;
                    if (cl + c > r1l) v1 = -1e30f;
                }
                s[nt][c] = v0; s[nt][2 + c] = v1;
                rm0 = fmaxf(rm0, v0); rm1 = fmaxf(rm1, v1);
            }
        }
        rm0 = fmaxf(rm0, __shfl_xor_sync(0xffffffffu, rm0, 1));
        rm0 = fmaxf(rm0, __shfl_xor_sync(0xffffffffu, rm0, 2));
        rm1 = fmaxf(rm1, __shfl_xor_sync(0xffffffffu, rm1, 1));
        rm1 = fmaxf(rm1, __shfl_xor_sync(0xffffffffu, rm1, 2));

        float mn0 = fmaxf(mrow[0], rm0), mn1 = fmaxf(mrow[1], rm1);
        float fc0 = __expf(mrow[0] - mn0), fc1 = __expf(mrow[1] - mn1);
        float rs0 = 0.f, rs1 = 0.f;
#pragma unroll
        for (int nt = 0; nt < 16; nt++) {
#pragma unroll
            for (int c = 0; c < 2; c++) {
                float p0 = __expf(s[nt][c] - mn0);
                float p1 = __expf(s[nt][2 + c] - mn1);
                s[nt][c] = p0; s[nt][2 + c] = p1;
                rs0 += p0; rs1 += p1;
            }
        }
        rs0 += __shfl_xor_sync(0xffffffffu, rs0, 1);
        rs0 += __shfl_xor_sync(0xffffffffu, rs0, 2);
        rs1 += __shfl_xor_sync(0xffffffffu, rs1, 1);
        rs1 += __shfl_xor_sync(0xffffffffu, rs1, 2);

        lrow[0] = lrow[0] * fc0 + rs0;
        lrow[1] = lrow[1] * fc1 + rs1;
        mrow[0] = mn0; mrow[1] = mn1;
#pragma unroll
        for (int nt = 0; nt < 8; nt++) {
            o[nt][0] *= fc0; o[nt][1] *= fc0;
            o[nt][2] *= fc1; o[nt][3] *= fc1;
        }

        // ---- in-register S-fragment -> PV A-fragment conversion ----
        // s[nt] holds (row g: cols 2ctg,2ctg+1 | row g+8: cols 2ctg,2ctg+1)
        // target     (a0: row g col ctg, a1: row g+8 col ctg,
        //             a2: row g col ctg+4, a3: row g+8 col ctg+4)
#pragma unroll
        for (int nt = 0; nt < 16; nt++) {
            float t0 = __shfl_sync(0xffffffffu, s[nt][0], src0);
            float t1 = __shfl_sync(0xffffffffu, s[nt][1], src0);
            float u0 = __shfl_sync(0xffffffffu, s[nt][0], src1);
            float u1 = __shfl_sync(0xffffffffu, s[nt][1], src1);
            float v0 = __shfl_sync(0xffffffffu, s[nt][2], src0);
            float v1 = __shfl_sync(0xffffffffu, s[nt][3], src0);
            float w0 = __shfl_sync(0xffffffffu, s[nt][2], src1);
            float w1 = __shfl_sync(0xffffffffu, s[nt][3], src1);
            s[nt][0] = codd ? t1 : t0;
            s[nt][1] = codd ? v1 : v0;
            s[nt][2] = codd ? u1 : u0;
            s[nt][3] = codd ? w1 : w0;
        }

        // ---- O += P V : warp tile 16 x 64, K=128 (A-frags from registers) ----
#pragma unroll
        for (int ks = 0; ks < 16; ks++) {
            const int kb = ks * 8;
            uint32_t a[4];
            a[0] = __float_as_uint(s[ks][0]);
            a[1] = __float_as_uint(s[ks][1]);
            a[2] = __float_as_uint(s[ks][2]);
            a[3] = __float_as_uint(s[ks][3]);
#pragma unroll
            for (int nt = 0; nt < 8; nt++) {
                uint32_t bb[2];
                bb[0] = __float_as_uint(VT[(nt * 8 + g) * VP + kb + ctg]);
                bb[1] = __float_as_uint(VT[(nt * 8 + g) * VP + kb + ctg + 4]);
                mma_tf32(o[nt], a, bb);
            }
        }
    }

    // ---- epilogue: normalize, end-token row mask, store ----
    const int limit = g_limit[b];
    const float qnan = __int_as_float(0x7FC00000);
    const int q0g = q0 + qw + g;
    const float inv0 = 1.f / lrow[0];
    const float inv1 = 1.f / lrow[1];
#pragma unroll
    for (int nt = 0; nt < 8; nt++) {
        int col = nt * 8 + 2 * ctg;
        float2 r0v, r1v;
        if (q0g >= limit) r0v = make_float2(qnan, qnan);
        else r0v = make_float2(o[nt][0] * inv0, o[nt][1] * inv0);
        if (q0g + 8 >= limit) r1v = make_float2(qnan, qnan);
        else r1v = make_float2(o[nt][2] * inv1, o[nt][3] * inv1);
        *reinterpret_cast<float2*>(&out[((size_t)b * SEQ + q0g) * HDIM + col]) = r0v;
        *reinterpret_cast<float2*>(&out[((size_t)b * SEQ + q0g + 8) * HDIM + col]) = r1v;
    }
}

// ---------------------------------------------------------------------------
extern "C" void kernel_launch(void* const* d_in, const int* in_sizes, int n_in,
                              void* d_out, int out_size)
{
    const float* x  = (const float*)d_in[0];
    const float* Wk = (const float*)d_in[1];
    const float* Wq = (const float*)d_in[2];
    const float* Wv = (const float*)d_in[3];
    const int*  idx = (const int*)d_in[4];
    float* out = (float*)d_out;

    (void)in_sizes; (void)n_in; (void)out_size;

    cudaFuncSetAttribute(attn_kernel,
                         cudaFuncAttributeMaxDynamicSharedMemorySize,
                         ATTN_SMEM_BYTES);

    transpose_w_kernel<<<48, 256>>>(Wk, Wq, Wv);
    proj_kernel<<<dim3(ROWS_TOTAL / 128, 2), 256>>>(x);
    limit_kernel<<<BATCH, 256>>>(idx);
    attn_kernel<<<dim3(SEQ / 128, BATCH), 256, ATTN_SMEM_BYTES>>>(out);
}

// round 8
// speedup vs baseline: 1.3765x; 1.3765x over previous
#include <cuda_runtime.h>
#include <cuda_bf16.h>
#include <math_constants.h>
#include <cstdint>

// Problem shape (fixed): B=16, T=2048, C=512, H=64
#define BATCH 16
#define SEQ   2048
#define CDIM  512
#define HDIM  64
#define END_TOKEN 32000

#define ROWS_TOTAL (BATCH * SEQ)          // 32768
#define SCALE 0.04419417382415922f        // 512^-0.5

__device__ __forceinline__ float tf32r(float x) {
    float y; asm("cvt.rna.tf32.f32 %0,%1;" : "=f"(y) : "f"(x)); return y;
}
__device__ __forceinline__ uint32_t smem_u32(const void* p) {
    uint32_t a;
    asm("{ .reg .u64 t; cvta.to.shared.u64 t, %1; cvt.u32.u64 %0, t; }"
        : "=r"(a) : "l"(p));
    return a;
}
__device__ __forceinline__ void cp16(uint32_t dst, const void* src) {
    asm volatile("cp.async.cg.shared.global [%0], [%1], 16;"
                 :: "r"(dst), "l"(src) : "memory");
}
#define CP_COMMIT() asm volatile("cp.async.commit_group;" ::: "memory")
#define CP_WAIT0()  asm volatile("cp.async.wait_group 0;" ::: "memory")

// m16n8k8 tf32 mma (sm_80 portable feature -> fallback HMMA on sm_103)
__device__ __forceinline__ void mma_tf32(float* d, const uint32_t* a, const uint32_t* b) {
    asm volatile(
        "mma.sync.aligned.m16n8k8.row.col.f32.tf32.tf32.f32 "
        "{%0,%1,%2,%3}, {%4,%5,%6,%7}, {%8,%9}, {%0,%1,%2,%3};"
        : "+f"(d[0]), "+f"(d[1]), "+f"(d[2]), "+f"(d[3])
        : "r"(a[0]), "r"(a[1]), "r"(a[2]), "r"(a[3]), "r"(b[0]), "r"(b[1]));
}

// Scratch (allocation-free rule: __device__ globals)
__device__ float g_q[ROWS_TOTAL * HDIM];           // tf32-rounded
__device__ float g_k[ROWS_TOTAL * HDIM];           // tf32-rounded
__device__ float g_vt[BATCH * HDIM * SEQ];         // V transposed [b][h][t], tf32-rounded
__device__ float g_wt[3 * HDIM * CDIM];            // W^T, tf32-rounded: [mat][n][k]
__device__ int   g_limit[BATCH];

// ---------------------------------------------------------------------------
// Kernel 0: transpose W -> g_wt[m][n][k] (K-major) with tf32 rounding.
// ---------------------------------------------------------------------------
__global__ void transpose_w_kernel(const float* __restrict__ Wk,
                                   const float* __restrict__ Wq,
                                   const float* __restrict__ Wv)
{
    const int m  = blockIdx.x / 16;
    const int ks = blockIdx.x % 16;           // k-slice of 32
    const float* src = (m == 0) ? Wq : (m == 1) ? Wk : Wv;
    float* dst = g_wt + (size_t)m * HDIM * CDIM;
    for (int i = threadIdx.x; i < 32 * 64; i += 256) {
        int k = ks * 32 + (i >> 6);
        int n = i & 63;
        dst[(size_t)n * CDIM + k] = tf32r(src[(size_t)k * HDIM + n]);
    }
}

// ---------------------------------------------------------------------------
// Kernel 1: QKV projection via tf32 mma.sync (R6 shape: 64 rows x 192 cols).
// Epilogue: tf32-round outputs; V written transposed to g_vt[b][h][t].
// ---------------------------------------------------------------------------
__global__ __launch_bounds__(256) void proj_kernel(const float* __restrict__ x)
{
    __shared__ float As[64][36];
    __shared__ float Bs[192][36];

    const int t    = threadIdx.x;
    const int wid  = t >> 5;
    const int lane = t & 31;
    const int g    = lane >> 2;
    const int ctg  = lane & 3;
    const int wm   = wid >> 2;     // 0..1
    const int wn   = wid & 3;      // 0..3
    const int row0 = blockIdx.x * 64;

    float acc[2][6][4];
#pragma unroll
    for (int mt = 0; mt < 2; mt++)
#pragma unroll
        for (int nt = 0; nt < 6; nt++)
#pragma unroll
            for (int i = 0; i < 4; i++) acc[mt][nt][i] = 0.f;

    for (int kc = 0; kc < 16; kc++) {
        // stage A: 64 rows x 32, tf32-rounded
        {
            int r = t >> 2, f = (t & 3) * 8;
            const float* xp = x + (size_t)(row0 + r) * CDIM + kc * 32 + f;
            float4 u = *reinterpret_cast<const float4*>(xp);
            float4 v = *reinterpret_cast<const float4*>(xp + 4);
            As[r][f + 0] = tf32r(u.x); As[r][f + 1] = tf32r(u.y);
            As[r][f + 2] = tf32r(u.z); As[r][f + 3] = tf32r(u.w);
            As[r][f + 4] = tf32r(v.x); As[r][f + 5] = tf32r(v.y);
            As[r][f + 6] = tf32r(v.z); As[r][f + 7] = tf32r(v.w);
        }
        // stage B: 192 rows x 32 (pre-rounded)
#pragma unroll
        for (int i = 0; i < 3; i++) {
            int u  = t + 256 * i;
            int r  = u >> 2, f = (u & 3) * 8;
            const float* wp = g_wt + (size_t)r * CDIM + kc * 32 + f;
            float4 a = *reinterpret_cast<const float4*>(wp);
            float4 bx = *reinterpret_cast<const float4*>(wp + 4);
            *reinterpret_cast<float4*>(&Bs[r][f])     = a;
            *reinterpret_cast<float4*>(&Bs[r][f + 4]) = bx;
        }
        __syncthreads();

#pragma unroll
        for (int ks = 0; ks < 4; ks++) {
            const int kb = ks * 8;
            uint32_t a[2][4];
#pragma unroll
            for (int mt = 0; mt < 2; mt++) {
                int row = wm * 32 + mt * 16;
                a[mt][0] = __float_as_uint(As[row + g][kb + ctg]);
                a[mt][1] = __float_as_uint(As[row + g + 8][kb + ctg]);
                a[mt][2] = __float_as_uint(As[row + g][kb + ctg + 4]);
                a[mt][3] = __float_as_uint(As[row + g + 8][kb + ctg + 4]);
            }
            uint32_t b[6][2];
#pragma unroll
            for (int nt = 0; nt < 6; nt++) {
                int n = wn * 48 + nt * 8;
                b[nt][0] = __float_as_uint(Bs[n + g][kb + ctg]);
                b[nt][1] = __float_as_uint(Bs[n + g][kb + ctg + 4]);
            }
#pragma unroll
            for (int mt = 0; mt < 2; mt++)
#pragma unroll
                for (int nt = 0; nt < 6; nt++)
                    mma_tf32(acc[mt][nt], a[mt], b[nt]);
        }
        __syncthreads();
    }

    // epilogue: Q/K row-major rounded; V transposed into g_vt[b][h][t]
#pragma unroll
    for (int mt = 0; mt < 2; mt++) {
#pragma unroll
        for (int nt = 0; nt < 6; nt++) {
            int col = wn * 48 + nt * 8 + 2 * ctg;
            int mat = col >> 6, cc = col & 63;
            int r0 = row0 + wm * 32 + mt * 16 + g;
            if (mat < 2) {
                float* gp = (mat == 0) ? g_q : g_k;
                *reinterpret_cast<float2*>(gp + (size_t)r0 * HDIM + cc) =
                    make_float2(tf32r(acc[mt][nt][0]), tf32r(acc[mt][nt][1]));
                *reinterpret_cast<float2*>(gp + (size_t)(r0 + 8) * HDIM + cc) =
                    make_float2(tf32r(acc[mt][nt][2]), tf32r(acc[mt][nt][3]));
            } else {
                int b  = r0 >> 11;
                int tp = r0 & 2047;
                float* vb = g_vt + ((size_t)b * HDIM + cc) * SEQ;
                vb[tp]            = tf32r(acc[mt][nt][0]);
                vb[SEQ + tp]      = tf32r(acc[mt][nt][1]);
                vb[tp + 8]        = tf32r(acc[mt][nt][2]);
                vb[SEQ + tp + 8]  = tf32r(acc[mt][nt][3]);
            }
        }
    }
}

// ---------------------------------------------------------------------------
// Kernel 2: end-token scan per batch (faithful; never fires for this dataset).
// ---------------------------------------------------------------------------
__global__ void limit_kernel(const int* __restrict__ idx)
{
    __shared__ int best;
    if (threadIdx.x == 0) best = SEQ;
    __syncthreads();
    const int b = blockIdx.x;
    for (int t = threadIdx.x; t < SEQ; t += blockDim.x)
        if (idx[(size_t)b * SEQ + t] == END_TOKEN) atomicMin(&best, t);
    __syncthreads();
    if (threadIdx.x == 0) g_limit[b] = best;
}

// ---------------------------------------------------------------------------
// Kernel 3: causal flash attention via tf32 mma.sync.
// CTA tile 128q; k processed in 64-col blocks, cp.async double-buffered.
// 8 warps x 16 q-rows; P stays in registers (quad-shuffle S->A conversion).
// smem: Qs[128][68] + 2x Ks[64][68] + 2x Vs[64][68] = 104,448 B -> 2 CTAs/SM.
// ---------------------------------------------------------------------------
#define QP 68
#define OFF_KB(buf) (128 * QP + (buf) * 64 * QP)
#define OFF_VB(buf) (128 * QP + 2 * 64 * QP + (buf) * 64 * QP)
#define ATTN_SMEM_FLOATS (128 * QP + 4 * 64 * QP)
#define ATTN_SMEM_BYTES (ATTN_SMEM_FLOATS * 4)

__global__ __launch_bounds__(256, 2) void attn_kernel(float* __restrict__ out)
{
    extern __shared__ float smf[];
    const uint32_t smb = smem_u32(smf);

    const int t    = threadIdx.x;
    const int wid  = t >> 5;
    const int lane = t & 31;
    const int g    = lane >> 2;
    const int ctg  = lane & 3;
    const int qw   = wid * 16;
    const int b    = blockIdx.y;
    const int qt   = (gridDim.x - 1) - blockIdx.x;   // heavy tiles first
    const int q0   = qt * 128;
    const int nk   = 2 * qt + 2;                     // number of 64-col k-blocks

    const float* kg0 = g_k  + ((size_t)b * SEQ) * HDIM;
    const float* vg0 = g_vt + ((size_t)b * HDIM) * SEQ;

    // stage Q (cp.async, pre-rounded): 2048 16B-chunks, 8/thread
    {
        const float* qg = g_q + ((size_t)b * SEQ + q0) * HDIM;
#pragma unroll
        for (int i = 0; i < 8; i++) {
            int idx = t + 256 * i;
            int r = idx >> 4, c = (idx & 15) * 4;
            cp16(smb + (uint32_t)(r * QP + c) * 4, qg + (size_t)r * HDIM + c);
        }
    }
    // stage K/V block 0 into buf 0
    {
#pragma unroll
        for (int i = 0; i < 4; i++) {
            int idx = t + 256 * i;
            int r = idx >> 4, c = (idx & 15) * 4;
            cp16(smb + (uint32_t)(OFF_KB(0) + r * QP + c) * 4,
                 kg0 + (size_t)r * HDIM + c);
            cp16(smb + (uint32_t)(OFF_VB(0) + r * QP + c) * 4,
                 vg0 + (size_t)r * SEQ + c);
        }
    }
    CP_COMMIT(); CP_WAIT0(); __syncthreads();

    float mrow[2] = { -CUDART_INF_F, -CUDART_INF_F };
    float lrow[2] = { 0.f, 0.f };
    float o[8][4];
#pragma unroll
    for (int nt = 0; nt < 8; nt++)
#pragma unroll
        for (int i = 0; i < 4; i++) o[nt][i] = 0.f;

    const int src0 = (lane & ~3) + (ctg >> 1);
    const int src1 = src0 + 2;
    const bool codd = (ctg & 1);

    for (int kt = 0; kt < nk; kt++) {
        const int cur = kt & 1;

        // prefetch next k-block into the other buffer
        if (kt + 1 < nk) {
            const float* kg = kg0 + (size_t)(kt + 1) * 64 * HDIM;
            const float* vg = vg0 + (size_t)(kt + 1) * 64;
#pragma unroll
            for (int i = 0; i < 4; i++) {
                int idx = t + 256 * i;
                int r = idx >> 4, c = (idx & 15) * 4;
                cp16(smb + (uint32_t)(OFF_KB(cur ^ 1) + r * QP + c) * 4,
                     kg + (size_t)r * HDIM + c);
                cp16(smb + (uint32_t)(OFF_VB(cur ^ 1) + r * QP + c) * 4,
                     vg + (size_t)r * SEQ + c);
            }
        }
        CP_COMMIT();

        const float* Kb = smf + OFF_KB(cur);
        const float* Vb = smf + OFF_VB(cur);

        // ---- S = Q K^T : warp tile 16 x 64 (8 n-tiles) ----
        float s[8][4];
#pragma unroll
        for (int nt = 0; nt < 8; nt++)
#pragma unroll
            for (int i = 0; i < 4; i++) s[nt][i] = 0.f;

#pragma unroll
        for (int ks = 0; ks < 8; ks++) {
            const int kb = ks * 8;
            uint32_t a[4];
            a[0] = __float_as_uint(smf[(qw + g) * QP + kb + ctg]);
            a[1] = __float_as_uint(smf[(qw + g + 8) * QP + kb + ctg]);
            a[2] = __float_as_uint(smf[(qw + g) * QP + kb + ctg + 4]);
            a[3] = __float_as_uint(smf[(qw + g + 8) * QP + kb + ctg + 4]);
#pragma unroll
            for (int nt = 0; nt < 8; nt++) {
                uint32_t bb[2];
                bb[0] = __float_as_uint(Kb[(nt * 8 + g) * QP + kb + ctg]);
                bb[1] = __float_as_uint(Kb[(nt * 8 + g) * QP + kb + ctg + 4]);
                mma_tf32(s[nt], a, bb);
            }
        }

        // ---- scale + causal mask + online softmax (rows g, g+8) ----
        const bool tail = (kt >= nk - 2);
        const int r0gl = q0 + qw + g, r1gl = r0gl + 8;
        const int kbase = kt * 64;
        float rm0 = -CUDART_INF_F, rm1 = -CUDART_INF_F;
#pragma unroll
        for (int nt = 0; nt < 8; nt++) {
            int cl = kbase + nt * 8 + 2 * ctg;
#pragma unroll
            for (int c = 0; c < 2; c++) {
                float v0 = s[nt][c] * SCALE;
                float v1 = s[nt][2 + c] * SCALE;
                if (tail) {
                    if (cl + c > r0gl) v0 = -1e30f;
                    if (cl + c > r1gl) v1 = -1e30f;
                }
                s[nt][c] = v0; s[nt][2 + c] = v1;
                rm0 = fmaxf(rm0, v0); rm1 = fmaxf(rm1, v1);
            }
        }
        rm0 = fmaxf(rm0, __shfl_xor_sync(0xffffffffu, rm0, 1));
        rm0 = fmaxf(rm0, __shfl_xor_sync(0xffffffffu, rm0, 2));
        rm1 = fmaxf(rm1, __shfl_xor_sync(0xffffffffu, rm1, 1));
        rm1 = fmaxf(rm1, __shfl_xor_sync(0xffffffffu, rm1, 2));

        float mn0 = fmaxf(mrow[0], rm0), mn1 = fmaxf(mrow[1], rm1);
        float fc0 = __expf(mrow[0] - mn0), fc1 = __expf(mrow[1] - mn1);
        float rs0 = 0.f, rs1 = 0.f;
#pragma unroll
        for (int nt = 0; nt < 8; nt++) {
#pragma unroll
            for (int c = 0; c < 2; c++) {
                float p0 = __expf(s[nt][c] - mn0);
                float p1 = __expf(s[nt][2 + c] - mn1);
                s[nt][c] = p0; s[nt][2 + c] = p1;
                rs0 += p0; rs1 += p1;
            }
        }
        rs0 += __shfl_xor_sync(0xffffffffu, rs0, 1);
        rs0 += __shfl_xor_sync(0xffffffffu, rs0, 2);
        rs1 += __shfl_xor_sync(0xffffffffu, rs1, 1);
        rs1 += __shfl_xor_sync(0xffffffffu, rs1, 2);

        lrow[0] = lrow[0] * fc0 + rs0;
        lrow[1] = lrow[1] * fc1 + rs1;
        mrow[0] = mn0; mrow[1] = mn1;
#pragma unroll
        for (int nt = 0; nt < 8; nt++) {
            o[nt][0] *= fc0; o[nt][1] *= fc0;
            o[nt][2] *= fc1; o[nt][3] *= fc1;
        }

        // ---- in-register S-fragment -> PV A-fragment conversion ----
#pragma unroll
        for (int nt = 0; nt < 8; nt++) {
            float t0 = __shfl_sync(0xffffffffu, s[nt][0], src0);
            float t1 = __shfl_sync(0xffffffffu, s[nt][1], src0);
            float u0 = __shfl_sync(0xffffffffu, s[nt][0], src1);
            float u1 = __shfl_sync(0xffffffffu, s[nt][1], src1);
            float v0 = __shfl_sync(0xffffffffu, s[nt][2], src0);
            float v1 = __shfl_sync(0xffffffffu, s[nt][3], src0);
            float w0 = __shfl_sync(0xffffffffu, s[nt][2], src1);
            float w1 = __shfl_sync(0xffffffffu, s[nt][3], src1);
            s[nt][0] = codd ? t1 : t0;
            s[nt][1] = codd ? v1 : v0;
            s[nt][2] = codd ? u1 : u0;
            s[nt][3] = codd ? w1 : w0;
        }

        // ---- O += P V : warp tile 16 x 64, K=64 ----
#pragma unroll
        for (int ks = 0; ks < 8; ks++) {
            const int kb = ks * 8;
            uint32_t a[4];
            a[0] = __float_as_uint(s[ks][0]);
            a[1] = __float_as_uint(s[ks][1]);
            a[2] = __float_as_uint(s[ks][2]);
            a[3] = __float_as_uint(s[ks][3]);
#pragma unroll
            for (int nt = 0; nt < 8; nt++) {
                uint32_t bb[2];
                bb[0] = __float_as_uint(Vb[(nt * 8 + g) * QP + kb + ctg]);
                bb[1] = __float_as_uint(Vb[(nt * 8 + g) * QP + kb + ctg + 4]);
                mma_tf32(o[nt], a, bb);
            }
        }

        CP_WAIT0();
        __syncthreads();
    }

    // ---- epilogue: normalize, end-token row mask, store ----
    const int limit = g_limit[b];
    const float qnan = __int_as_float(0x7FC00000);
    const int q0g = q0 + qw + g;
    const float inv0 = 1.f / lrow[0];
    const float inv1 = 1.f / lrow[1];
#pragma unroll
    for (int nt = 0; nt < 8; nt++) {
        int col = nt * 8 + 2 * ctg;
        float2 r0v, r1v;
        if (q0g >= limit) r0v = make_float2(qnan, qnan);
        else r0v = make_float2(o[nt][0] * inv0, o[nt][1] * inv0);
        if (q0g + 8 >= limit) r1v = make_float2(qnan, qnan);
        else r1v = make_float2(o[nt][2] * inv1, o[nt][3] * inv1);
        *reinterpret_cast<float2*>(&out[((size_t)b * SEQ + q0g) * HDIM + col]) = r0v;
        *reinterpret_cast<float2*>(&out[((size_t)b * SEQ + q0g + 8) * HDIM + col]) = r1v;
    }
}

// ---------------------------------------------------------------------------
extern "C" void kernel_launch(void* const* d_in, const int* in_sizes, int n_in,
                              void* d_out, int out_size)
{
    const float* x  = (const float*)d_in[0];
    const float* Wk = (const float*)d_in[1];
    const float* Wq = (const float*)d_in[2];
    const float* Wv = (const float*)d_in[3];
    const int*  idx = (const int*)d_in[4];
    float* out = (float*)d_out;

    (void)in_sizes; (void)n_in; (void)out_size;

    cudaFuncSetAttribute(attn_kernel,
                         cudaFuncAttributeMaxDynamicSharedMemorySize,
                         ATTN_SMEM_BYTES);

    transpose_w_kernel<<<48, 256>>>(Wk, Wq, Wv);
    proj_kernel<<<ROWS_TOTAL / 64, 256>>>(x);
    limit_kernel<<<BATCH, 256>>>(idx);
    attn_kernel<<<dim3(SEQ / 128, BATCH), 256, ATTN_SMEM_BYTES>>>(out);
}

// round 9
// speedup vs baseline: 1.5311x; 1.1123x over previous
#include <cuda_runtime.h>
#include <cuda_bf16.h>
#include <math_constants.h>
#include <cstdint>

// Problem shape (fixed): B=16, T=2048, C=512, H=64
#define BATCH 16
#define SEQ   2048
#define CDIM  512
#define HDIM  64
#define END_TOKEN 32000

#define ROWS_TOTAL (BATCH * SEQ)          // 32768
#define SCALE 0.04419417382415922f        // 512^-0.5

__device__ __forceinline__ float tf32r(float x) {
    float y; asm("cvt.rna.tf32.f32 %0,%1;" : "=f"(y) : "f"(x)); return y;
}
__device__ __forceinline__ uint32_t smem_u32(const void* p) {
    uint32_t a;
    asm("{ .reg .u64 t; cvta.to.shared.u64 t, %1; cvt.u32.u64 %0, t; }"
        : "=r"(a) : "l"(p));
    return a;
}
__device__ __forceinline__ void cp16(uint32_t dst, const void* src) {
    asm volatile("cp.async.cg.shared.global [%0], [%1], 16;"
                 :: "r"(dst), "l"(src) : "memory");
}
#define CP_COMMIT() asm volatile("cp.async.commit_group;" ::: "memory")
#define CP_WAIT0()  asm volatile("cp.async.wait_group 0;" ::: "memory")

// pair-permutation within 8: 0,4,1,5,2,6,3,7  (puts (i, i+4) adjacent)
__device__ __forceinline__ int perm8(int i) {
    return (i & ~7) | ((i & 3) << 1) | ((i >> 2) & 1);
}

// m16n8k8 tf32 mma (sm_80 portable feature -> fallback HMMA on sm_103)
__device__ __forceinline__ void mma_tf32(float* d, const uint32_t* a, const uint32_t* b) {
    asm volatile(
        "mma.sync.aligned.m16n8k8.row.col.f32.tf32.tf32.f32 "
        "{%0,%1,%2,%3}, {%4,%5,%6,%7}, {%8,%9}, {%0,%1,%2,%3};"
        : "+f"(d[0]), "+f"(d[1]), "+f"(d[2]), "+f"(d[3])
        : "r"(a[0]), "r"(a[1]), "r"(a[2]), "r"(a[3]), "r"(b[0]), "r"(b[1]));
}

// Scratch (allocation-free rule: __device__ globals)
// g_q/g_k: [row][perm8(h)] tf32-rounded.  g_vt: [b][h][perm8-in-8 of t].
__device__ float g_q[ROWS_TOTAL * HDIM];
__device__ float g_k[ROWS_TOTAL * HDIM];
__device__ float g_vt[BATCH * HDIM * SEQ];
__device__ float g_wt[3 * HDIM * CDIM];            // W^T tf32: [mat][n][k]
__device__ int   g_limit[BATCH];

// ---------------------------------------------------------------------------
// Kernel 0: transpose W -> g_wt[m][n][k] (K-major) with tf32 rounding.
// ---------------------------------------------------------------------------
__global__ void transpose_w_kernel(const float* __restrict__ Wk,
                                   const float* __restrict__ Wq,
                                   const float* __restrict__ Wv)
{
    const int m  = blockIdx.x / 16;
    const int ks = blockIdx.x % 16;           // k-slice of 32
    const float* src = (m == 0) ? Wq : (m == 1) ? Wk : Wv;
    float* dst = g_wt + (size_t)m * HDIM * CDIM;
    for (int i = threadIdx.x; i < 32 * 64; i += 256) {
        int k = ks * 32 + (i >> 6);
        int n = i & 63;
        dst[(size_t)n * CDIM + k] = tf32r(src[(size_t)k * HDIM + n]);
    }
}

// ---------------------------------------------------------------------------
// Kernel 1: QKV projection via tf32 mma.sync (64 rows x 192 cols per CTA).
// Epilogue: Q/K h-permuted; V transposed via smem -> coalesced g_vt writes.
// ---------------------------------------------------------------------------
__global__ __launch_bounds__(256) void proj_kernel(const float* __restrict__ x)
{
    __shared__ float sbuf[64 * 36 + 192 * 36];   // As | Bs ; reused as Vtr
    float* As = sbuf;                            // [64][36]
    float* Bs = sbuf + 64 * 36;                  // [192][36]

    const int t    = threadIdx.x;
    const int wid  = t >> 5;
    const int lane = t & 31;
    const int g    = lane >> 2;
    const int ctg  = lane & 3;
    const int wm   = wid >> 2;     // 0..1
    const int wn   = wid & 3;      // 0..3
    const int row0 = blockIdx.x * 64;

    float acc[2][6][4];
#pragma unroll
    for (int mt = 0; mt < 2; mt++)
#pragma unroll
        for (int nt = 0; nt < 6; nt++)
#pragma unroll
            for (int i = 0; i < 4; i++) acc[mt][nt][i] = 0.f;

    for (int kc = 0; kc < 16; kc++) {
        // stage A: 64 rows x 32, tf32-rounded
        {
            int r = t >> 2, f = (t & 3) * 8;
            const float* xp = x + (size_t)(row0 + r) * CDIM + kc * 32 + f;
            float4 u = *reinterpret_cast<const float4*>(xp);
            float4 v = *reinterpret_cast<const float4*>(xp + 4);
            float* a = &As[r * 36 + f];
            a[0] = tf32r(u.x); a[1] = tf32r(u.y); a[2] = tf32r(u.z); a[3] = tf32r(u.w);
            a[4] = tf32r(v.x); a[5] = tf32r(v.y); a[6] = tf32r(v.z); a[7] = tf32r(v.w);
        }
        // stage B: 192 rows x 32 (pre-rounded)
#pragma unroll
        for (int i = 0; i < 3; i++) {
            int u  = t + 256 * i;
            int r  = u >> 2, f = (u & 3) * 8;
            const float* wp = g_wt + (size_t)r * CDIM + kc * 32 + f;
            float4 a = *reinterpret_cast<const float4*>(wp);
            float4 bx = *reinterpret_cast<const float4*>(wp + 4);
            *reinterpret_cast<float4*>(&Bs[r * 36 + f])     = a;
            *reinterpret_cast<float4*>(&Bs[r * 36 + f + 4]) = bx;
        }
        __syncthreads();

#pragma unroll
        for (int ks = 0; ks < 4; ks++) {
            const int kb = ks * 8;
            uint32_t a[2][4];
#pragma unroll
            for (int mt = 0; mt < 2; mt++) {
                int row = wm * 32 + mt * 16;
                a[mt][0] = __float_as_uint(As[(row + g) * 36 + kb + ctg]);
                a[mt][1] = __float_as_uint(As[(row + g + 8) * 36 + kb + ctg]);
                a[mt][2] = __float_as_uint(As[(row + g) * 36 + kb + ctg + 4]);
                a[mt][3] = __float_as_uint(As[(row + g + 8) * 36 + kb + ctg + 4]);
            }
            uint32_t b[6][2];
#pragma unroll
            for (int nt = 0; nt < 6; nt++) {
                int n = wn * 48 + nt * 8;
                b[nt][0] = __float_as_uint(Bs[(n + g) * 36 + kb + ctg]);
                b[nt][1] = __float_as_uint(Bs[(n + g) * 36 + kb + ctg + 4]);
            }
#pragma unroll
            for (int mt = 0; mt < 2; mt++)
#pragma unroll
                for (int nt = 0; nt < 6; nt++)
                    mma_tf32(acc[mt][nt], a[mt], b[nt]);
        }
        __syncthreads();
    }

    // ---- epilogue ----
    // Q/K: row-major, h permuted within 8-blocks. V: into smem Vtr[h][64+pad].
    float* Vtr = sbuf;    // [64][68], reuse (all Bs/As reads are done)
#pragma unroll
    for (int mt = 0; mt < 2; mt++) {
#pragma unroll
        for (int nt = 0; nt < 6; nt++) {
            int col = wn * 48 + nt * 8 + 2 * ctg;
            int mat = col >> 6, c0 = col & 63;
            int r0 = row0 + wm * 32 + mt * 16 + g;
            if (mat < 2) {
                float* gp = (mat == 0) ? g_q : g_k;
                gp[(size_t)r0 * HDIM + perm8(c0)]           = tf32r(acc[mt][nt][0]);
                gp[(size_t)r0 * HDIM + perm8(c0 + 1)]       = tf32r(acc[mt][nt][1]);
                gp[(size_t)(r0 + 8) * HDIM + perm8(c0)]     = tf32r(acc[mt][nt][2]);
                gp[(size_t)(r0 + 8) * HDIM + perm8(c0 + 1)] = tf32r(acc[mt][nt][3]);
            } else {
                int tl = wm * 32 + mt * 16 + g;      // 0..55 (+8 below)
                Vtr[c0 * 68 + perm8(tl)]           = tf32r(acc[mt][nt][0]);
                Vtr[(c0 + 1) * 68 + perm8(tl)]     = tf32r(acc[mt][nt][1]);
                Vtr[c0 * 68 + perm8(tl + 8)]       = tf32r(acc[mt][nt][2]);
                Vtr[(c0 + 1) * 68 + perm8(tl + 8)] = tf32r(acc[mt][nt][3]);
            }
        }
    }
    __syncthreads();

    // coalesced V writes: 64 h-rows x 64 t (256B bursts)
    {
        const int b  = row0 >> 11;
        const int t0 = row0 & 2047;
#pragma unroll
        for (int i = 0; i < 4; i++) {
            int idx = t + 256 * i;
            int h = idx >> 4, c = (idx & 15) * 4;
            float4 v = *reinterpret_cast<const float4*>(&Vtr[h * 68 + c]);
            *reinterpret_cast<float4*>(
                &g_vt[((size_t)b * HDIM + h) * SEQ + t0 + c]) = v;
        }
    }
}

// ---------------------------------------------------------------------------
// Kernel 2: end-token scan per batch (faithful; never fires for this dataset).
// ---------------------------------------------------------------------------
__global__ void limit_kernel(const int* __restrict__ idx)
{
    __shared__ int best;
    if (threadIdx.x == 0) best = SEQ;
    __syncthreads();
    const int b = blockIdx.x;
    for (int t = threadIdx.x; t < SEQ; t += blockDim.x)
        if (idx[(size_t)b * SEQ + t] == END_TOKEN) atomicMin(&best, t);
    __syncthreads();
    if (threadIdx.x == 0) g_limit[b] = best;
}

// ---------------------------------------------------------------------------
// Kernel 3: causal flash attention via tf32 mma.sync.
// CTA tile 128q; 64-col k-blocks, cp.async double-buffered; P in registers.
// Paired (LDS.64) fragment loads via perm8 layout; QP=72 -> conflict-free.
// smem: Qs[128][72] + 2x K[64][72] + 2x V[64][72] = 110,592 B -> 2 CTAs/SM.
// ---------------------------------------------------------------------------
#define QP 72
#define OFF_KB(buf) (128 * QP + (buf) * 64 * QP)
#define OFF_VB(buf) (128 * QP + 2 * 64 * QP + (buf) * 64 * QP)
#define ATTN_SMEM_FLOATS (128 * QP + 4 * 64 * QP)
#define ATTN_SMEM_BYTES (ATTN_SMEM_FLOATS * 4)

__global__ __launch_bounds__(256, 2) void attn_kernel(float* __restrict__ out)
{
    extern __shared__ float smf[];
    const uint32_t smb = smem_u32(smf);

    const int t    = threadIdx.x;
    const int wid  = t >> 5;
    const int lane = t & 31;
    const int g    = lane >> 2;
    const int ctg  = lane & 3;
    const int qw   = wid * 16;
    const int b    = blockIdx.y;
    const int qt   = (gridDim.x - 1) - blockIdx.x;   // heavy tiles first
    const int q0   = qt * 128;
    const int nk   = 2 * qt + 2;                     // 64-col k-blocks

    const float* kg0 = g_k  + ((size_t)b * SEQ) * HDIM;
    const float* vg0 = g_vt + ((size_t)b * HDIM) * SEQ;

    // stage Q (cp.async, pre-rounded & permuted)
    {
        const float* qg = g_q + ((size_t)b * SEQ + q0) * HDIM;
#pragma unroll
        for (int i = 0; i < 8; i++) {
            int idx = t + 256 * i;
            int r = idx >> 4, c = (idx & 15) * 4;
            cp16(smb + (uint32_t)(r * QP + c) * 4, qg + (size_t)r * HDIM + c);
        }
    }
    // stage K/V block 0 into buf 0
    {
#pragma unroll
        for (int i = 0; i < 4; i++) {
            int idx = t + 256 * i;
            int r = idx >> 4, c = (idx & 15) * 4;
            cp16(smb + (uint32_t)(OFF_KB(0) + r * QP + c) * 4,
                 kg0 + (size_t)r * HDIM + c);
            cp16(smb + (uint32_t)(OFF_VB(0) + r * QP + c) * 4,
                 vg0 + (size_t)r * SEQ + c);
        }
    }
    CP_COMMIT(); CP_WAIT0(); __syncthreads();

    float mrow[2] = { -CUDART_INF_F, -CUDART_INF_F };
    float lrow[2] = { 0.f, 0.f };
    float o[8][4];
#pragma unroll
    for (int nt = 0; nt < 8; nt++)
#pragma unroll
        for (int i = 0; i < 4; i++) o[nt][i] = 0.f;

    const int src0 = (lane & ~3) + (ctg >> 1);
    const int src1 = src0 + 2;
    const bool codd = (ctg & 1);

    for (int kt = 0; kt < nk; kt++) {
        const int cur = kt & 1;

        // prefetch next k-block into the other buffer
        if (kt + 1 < nk) {
            const float* kg = kg0 + (size_t)(kt + 1) * 64 * HDIM;
            const float* vg = vg0 + (size_t)(kt + 1) * 64;
#pragma unroll
            for (int i = 0; i < 4; i++) {
                int idx = t + 256 * i;
                int r = idx >> 4, c = (idx & 15) * 4;
                cp16(smb + (uint32_t)(OFF_KB(cur ^ 1) + r * QP + c) * 4,
                     kg + (size_t)r * HDIM + c);
                cp16(smb + (uint32_t)(OFF_VB(cur ^ 1) + r * QP + c) * 4,
                     vg + (size_t)r * SEQ + c);
            }
        }
        CP_COMMIT();

        const float* Kb = smf + OFF_KB(cur);
        const float* Vb = smf + OFF_VB(cur);

        // ---- S = Q K^T : warp tile 16 x 64 (paired LDS.64 fragments) ----
        float s[8][4];
#pragma unroll
        for (int nt = 0; nt < 8; nt++)
#pragma unroll
            for (int i = 0; i < 4; i++) s[nt][i] = 0.f;

#pragma unroll
        for (int ks = 0; ks < 8; ks++) {
            const int kb = ks * 8 + 2 * ctg;
            float2 qa0 = *reinterpret_cast<const float2*>(&smf[(qw + g) * QP + kb]);
            float2 qa1 = *reinterpret_cast<const float2*>(&smf[(qw + g + 8) * QP + kb]);
            uint32_t a[4];
            a[0] = __float_as_uint(qa0.x); a[1] = __float_as_uint(qa1.x);
            a[2] = __float_as_uint(qa0.y); a[3] = __float_as_uint(qa1.y);
#pragma unroll
            for (int nt = 0; nt < 8; nt++) {
                float2 kf = *reinterpret_cast<const float2*>(&Kb[(nt * 8 + g) * QP + kb]);
                uint32_t bb[2];
                bb[0] = __float_as_uint(kf.x); bb[1] = __float_as_uint(kf.y);
                mma_tf32(s[nt], a, bb);
            }
        }

        // ---- scale + causal mask + online softmax (rows g, g+8) ----
        const bool tail = (kt >= nk - 2);
        const int r0gl = q0 + qw + g, r1gl = r0gl + 8;
        const int kbase = kt * 64;
        float rm0 = -CUDART_INF_F, rm1 = -CUDART_INF_F;
#pragma unroll
        for (int nt = 0; nt < 8; nt++) {
            int cl = kbase + nt * 8 + 2 * ctg;
#pragma unroll
            for (int c = 0; c < 2; c++) {
                float v0 = s[nt][c] * SCALE;
                float v1 = s[nt][2 + c] * SCALE;
                if (tail) {
                    if (cl + c > r0gl) v0 = -1e30f;
                    if (cl + c > r1gl) v1 = -1e30f;
                }
                s[nt][c] = v0; s[nt][2 + c] = v1;
                rm0 = fmaxf(rm0, v0); rm1 = fmaxf(rm1, v1);
            }
        }
        rm0 = fmaxf(rm0, __shfl_xor_sync(0xffffffffu, rm0, 1));
        rm0 = fmaxf(rm0, __shfl_xor_sync(0xffffffffu, rm0, 2));
        rm1 = fmaxf(rm1, __shfl_xor_sync(0xffffffffu, rm1, 1));
        rm1 = fmaxf(rm1, __shfl_xor_sync(0xffffffffu, rm1, 2));

        float mn0 = fmaxf(mrow[0], rm0), mn1 = fmaxf(mrow[1], rm1);
        float fc0 = __expf(mrow[0] - mn0), fc1 = __expf(mrow[1] - mn1);
        float rs0 = 0.f, rs1 = 0.f;
#pragma unroll
        for (int nt = 0; nt < 8; nt++) {
#pragma unroll
            for (int c = 0; c < 2; c++) {
                float p0 = __expf(s[nt][c] - mn0);
                float p1 = __expf(s[nt][2 + c] - mn1);
                s[nt][c] = p0; s[nt][2 + c] = p1;
                rs0 += p0; rs1 += p1;
            }
        }
        rs0 += __shfl_xor_sync(0xffffffffu, rs0, 1);
        rs0 += __shfl_xor_sync(0xffffffffu, rs0, 2);
        rs1 += __shfl_xor_sync(0xffffffffu, rs1, 1);
        rs1 += __shfl_xor_sync(0xffffffffu, rs1, 2);

        lrow[0] = lrow[0] * fc0 + rs0;
        lrow[1] = lrow[1] * fc1 + rs1;
        mrow[0] = mn0; mrow[1] = mn1;
#pragma unroll
        for (int nt = 0; nt < 8; nt++) {
            o[nt][0] *= fc0; o[nt][1] *= fc0;
            o[nt][2] *= fc1; o[nt][3] *= fc1;
        }

        // ---- in-register S-fragment -> PV A-fragment conversion ----
#pragma unroll
        for (int nt = 0; nt < 8; nt++) {
            float t0 = __shfl_sync(0xffffffffu, s[nt][0], src0);
            float t1 = __shfl_sync(0xffffffffu, s[nt][1], src0);
            float u0 = __shfl_sync(0xffffffffu, s[nt][0], src1);
            float u1 = __shfl_sync(0xffffffffu, s[nt][1], src1);
            float v0 = __shfl_sync(0xffffffffu, s[nt][2], src0);
            float v1 = __shfl_sync(0xffffffffu, s[nt][3], src0);
            float w0 = __shfl_sync(0xffffffffu, s[nt][2], src1);
            float w1 = __shfl_sync(0xffffffffu, s[nt][3], src1);
            s[nt][0] = codd ? t1 : t0;
            s[nt][1] = codd ? v1 : v0;
            s[nt][2] = codd ? u1 : u0;
            s[nt][3] = codd ? w1 : w0;
        }

        // ---- O += P V : warp tile 16 x 64, K=64 (paired V fragments) ----
#pragma unroll
        for (int ks = 0; ks < 8; ks++) {
            const int kb = ks * 8 + 2 * ctg;
            uint32_t a[4];
            a[0] = __float_as_uint(s[ks][0]);
            a[1] = __float_as_uint(s[ks][1]);
            a[2] = __float_as_uint(s[ks][2]);
            a[3] = __float_as_uint(s[ks][3]);
#pragma unroll
            for (int nt = 0; nt < 8; nt++) {
                float2 vf = *reinterpret_cast<const float2*>(&Vb[(nt * 8 + g) * QP + kb]);
                uint32_t bb[2];
                bb[0] = __float_as_uint(vf.x); bb[1] = __float_as_uint(vf.y);
                mma_tf32(o[nt], a, bb);
            }
        }

        CP_WAIT0();
        __syncthreads();
    }

    // ---- epilogue: normalize, end-token row mask, store ----
    const int limit = g_limit[b];
    const float qnan = __int_as_float(0x7FC00000);
    const int q0g = q0 + qw + g;
    const float inv0 = 1.f / lrow[0];
    const float inv1 = 1.f / lrow[1];
#pragma unroll
    for (int nt = 0; nt < 8; nt++) {
        int col = nt * 8 + 2 * ctg;
        float2 r0v, r1v;
        if (q0g >= limit) r0v = make_float2(qnan, qnan);
        else r0v = make_float2(o[nt][0] * inv0, o[nt][1] * inv0);
        if (q0g + 8 >= limit) r1v = make_float2(qnan, qnan);
        else r1v = make_float2(o[nt][2] * inv1, o[nt][3] * inv1);
        *reinterpret_cast<float2*>(&out[((size_t)b * SEQ + q0g) * HDIM + col]) = r0v;
        *reinterpret_cast<float2*>(&out[((size_t)b * SEQ + q0g + 8) * HDIM + col]) = r1v;
    }
}

// ---------------------------------------------------------------------------
extern "C" void kernel_launch(void* const* d_in, const int* in_sizes, int n_in,
                              void* d_out, int out_size)
{
    const float* x  = (const float*)d_in[0];
    const float* Wk = (const float*)d_in[1];
    const float* Wq = (const float*)d_in[2];
    const float* Wv = (const float*)d_in[3];
    const int*  idx = (const int*)d_in[4];
    float* out = (float*)d_out;

    (void)in_sizes; (void)n_in; (void)out_size;

    cudaFuncSetAttribute(attn_kernel,
                         cudaFuncAttributeMaxDynamicSharedMemorySize,
                         ATTN_SMEM_BYTES);

    transpose_w_kernel<<<48, 256>>>(Wk, Wq, Wv);
    proj_kernel<<<ROWS_TOTAL / 64, 256>>>(x);
    limit_kernel<<<BATCH, 256>>>(idx);
    attn_kernel<<<dim3(SEQ / 128, BATCH), 256, ATTN_SMEM_BYTES>>>(out);
}

// round 10
// speedup vs baseline: 1.7192x; 1.1229x over previous
#include <cuda_runtime.h>
#include <cuda_bf16.h>
#include <math_constants.h>
#include <cstdint>

// Problem shape (fixed): B=16, T=2048, C=512, H=64
#define BATCH 16
#define SEQ   2048
#define CDIM  512
#define HDIM  64
#define END_TOKEN 32000

#define ROWS_TOTAL (BATCH * SEQ)          // 32768
#define SCALE 0.04419417382415922f        // 512^-0.5
#define SCL2  0.06377946286456401f        // SCALE * log2(e)

__device__ __forceinline__ float tf32r(float x) {
    float y; asm("cvt.rna.tf32.f32 %0,%1;" : "=f"(y) : "f"(x)); return y;
}
__device__ __forceinline__ float ex2(float x) {
    float y; asm("ex2.approx.f32 %0,%1;" : "=f"(y) : "f"(x)); return y;
}
__device__ __forceinline__ uint32_t smem_u32(const void* p) {
    uint32_t a;
    asm("{ .reg .u64 t; cvta.to.shared.u64 t, %1; cvt.u32.u64 %0, t; }"
        : "=r"(a) : "l"(p));
    return a;
}
__device__ __forceinline__ void cp16(uint32_t dst, const void* src) {
    asm volatile("cp.async.cg.shared.global [%0], [%1], 16;"
                 :: "r"(dst), "l"(src) : "memory");
}
#define CP_COMMIT() asm volatile("cp.async.commit_group;" ::: "memory")
#define CP_WAIT0()  asm volatile("cp.async.wait_group 0;" ::: "memory")

// pair-permutation within 8: logical i -> physical (puts (i, i+4) adjacent)
__device__ __forceinline__ int perm8(int i) {
    return (i & ~7) | ((i & 3) << 1) | ((i >> 2) & 1);
}

// m16n8k8 tf32 mma (sm_80 portable feature -> fallback HMMA on sm_103)
__device__ __forceinline__ void mma_tf32(float* d, const uint32_t* a, const uint32_t* b) {
    asm volatile(
        "mma.sync.aligned.m16n8k8.row.col.f32.tf32.tf32.f32 "
        "{%0,%1,%2,%3}, {%4,%5,%6,%7}, {%8,%9}, {%0,%1,%2,%3};"
        : "+f"(d[0]), "+f"(d[1]), "+f"(d[2]), "+f"(d[3])
        : "r"(a[0]), "r"(a[1]), "r"(a[2]), "r"(a[3]), "r"(b[0]), "r"(b[1]));
}

// Scratch (allocation-free rule: __device__ globals)
// g_q/g_k: [row][perm8(h)] tf32-rounded.  g_vt: [b][h][t] (t NOT permuted).
__device__ float g_q[ROWS_TOTAL * HDIM];
__device__ float g_k[ROWS_TOTAL * HDIM];
__device__ float g_vt[BATCH * HDIM * SEQ];
__device__ float g_wt[3 * HDIM * CDIM];   // W^T tf32: [mat][n][perm8(k)]
__device__ int   g_limit[BATCH];

// ---------------------------------------------------------------------------
// Kernel 0 (merged): blocks 0..47 transpose W (perm8 on k, tf32-rounded);
// blocks 48..63 run the end-token scan (faithful; never fires here).
// ---------------------------------------------------------------------------
__global__ void prep_kernel(const float* __restrict__ Wk,
                            const float* __restrict__ Wq,
                            const float* __restrict__ Wv,
                            const int* __restrict__ idx)
{
    if (blockIdx.x < 48) {
        const int m  = blockIdx.x / 16;
        const int ks = blockIdx.x % 16;           // k-slice of 32
        const float* src = (m == 0) ? Wq : (m == 1) ? Wk : Wv;
        float* dst = g_wt + (size_t)m * HDIM * CDIM;
        for (int i = threadIdx.x; i < 32 * 64; i += 256) {
            int k = ks * 32 + (i >> 6);
            int n = i & 63;
            dst[(size_t)n * CDIM + perm8(k)] = tf32r(src[(size_t)k * HDIM + n]);
        }
    } else {
        __shared__ int best;
        if (threadIdx.x == 0) best = SEQ;
        __syncthreads();
        const int b = blockIdx.x - 48;
        for (int t = threadIdx.x; t < SEQ; t += blockDim.x)
            if (idx[(size_t)b * SEQ + t] == END_TOKEN) atomicMin(&best, t);
        __syncthreads();
        if (threadIdx.x == 0) g_limit[b] = best;
    }
}

// ---------------------------------------------------------------------------
// Kernel 1: QKV projection via tf32 mma.sync (64 rows x 192 cols per CTA).
// perm8-paired fragment loads (LDS.64), register prefetch of next A/B chunk.
// Epilogue: Q/K h-permuted; V via smem transpose -> coalesced g_vt writes.
// ---------------------------------------------------------------------------
#define PJP 40

__global__ __launch_bounds__(256) void proj_kernel(const float* __restrict__ x)
{
    __shared__ float sbuf[64 * PJP + 192 * PJP];   // As | Bs ; reused as Vtr
    float* As = sbuf;                              // [64][PJP]
    float* Bs = sbuf + 64 * PJP;                   // [192][PJP]

    const int t    = threadIdx.x;
    const int wid  = t >> 5;
    const int lane = t & 31;
    const int g    = lane >> 2;
    const int ctg  = lane & 3;
    const int wm   = wid >> 2;     // 0..1
    const int wn   = wid & 3;      // 0..3
    const int row0 = blockIdx.x * 64;

    // staging coordinates
    const int ar = t >> 2, af = (t & 3) * 8;
    const int br0 = t >> 2,           bf0 = (t & 3) * 8;
    const int br1 = (t + 256) >> 2,   bf1 = ((t + 256) & 3) * 8;
    const int br2 = (t + 512) >> 2,   bf2 = ((t + 512) & 3) * 8;

    float acc[2][6][4];
#pragma unroll
    for (int mt = 0; mt < 2; mt++)
#pragma unroll
        for (int nt = 0; nt < 6; nt++)
#pragma unroll
            for (int i = 0; i < 4; i++) acc[mt][nt][i] = 0.f;

    float4 pa0, pa1, pb[6];
    {
        const float* xp = x + (size_t)(row0 + ar) * CDIM + af;
        pa0 = *reinterpret_cast<const float4*>(xp);
        pa1 = *reinterpret_cast<const float4*>(xp + 4);
        pb[0] = *reinterpret_cast<const float4*>(g_wt + (size_t)br0 * CDIM + bf0);
        pb[1] = *reinterpret_cast<const float4*>(g_wt + (size_t)br0 * CDIM + bf0 + 4);
        pb[2] = *reinterpret_cast<const float4*>(g_wt + (size_t)br1 * CDIM + bf1);
        pb[3] = *reinterpret_cast<const float4*>(g_wt + (size_t)br1 * CDIM + bf1 + 4);
        pb[4] = *reinterpret_cast<const float4*>(g_wt + (size_t)br2 * CDIM + bf2);
        pb[5] = *reinterpret_cast<const float4*>(g_wt + (size_t)br2 * CDIM + bf2 + 4);
    }

    for (int kc = 0; kc < 16; kc++) {
        // ---- store staged chunk (A: perm8 pairs via STS.64; B: raw copies) ----
        {
            float* a = &As[ar * PJP + af];
            *reinterpret_cast<float2*>(&a[0]) = make_float2(tf32r(pa0.x), tf32r(pa1.x));
            *reinterpret_cast<float2*>(&a[2]) = make_float2(tf32r(pa0.y), tf32r(pa1.y));
            *reinterpret_cast<float2*>(&a[4]) = make_float2(tf32r(pa0.z), tf32r(pa1.z));
            *reinterpret_cast<float2*>(&a[6]) = make_float2(tf32r(pa0.w), tf32r(pa1.w));
            *reinterpret_cast<float4*>(&Bs[br0 * PJP + bf0])     = pb[0];
            *reinterpret_cast<float4*>(&Bs[br0 * PJP + bf0 + 4]) = pb[1];
            *reinterpret_cast<float4*>(&Bs[br1 * PJP + bf1])     = pb[2];
            *reinterpret_cast<float4*>(&Bs[br1 * PJP + bf1 + 4]) = pb[3];
            *reinterpret_cast<float4*>(&Bs[br2 * PJP + bf2])     = pb[4];
            *reinterpret_cast<float4*>(&Bs[br2 * PJP + bf2 + 4]) = pb[5];
        }
        __syncthreads();

        // ---- prefetch next chunk into registers (hidden under MMAs) ----
        if (kc < 15) {
            const int ko = (kc + 1) * 32;
            const float* xp = x + (size_t)(row0 + ar) * CDIM + ko + af;
            pa0 = *reinterpret_cast<const float4*>(xp);
            pa1 = *reinterpret_cast<const float4*>(xp + 4);
            pb[0] = *reinterpret_cast<const float4*>(g_wt + (size_t)br0 * CDIM + ko + bf0);
            pb[1] = *reinterpret_cast<const float4*>(g_wt + (size_t)br0 * CDIM + ko + bf0 + 4);
            pb[2] = *reinterpret_cast<const float4*>(g_wt + (size_t)br1 * CDIM + ko + bf1);
            pb[3] = *reinterpret_cast<const float4*>(g_wt + (size_t)br1 * CDIM + ko + bf1 + 4);
            pb[4] = *reinterpret_cast<const float4*>(g_wt + (size_t)br2 * CDIM + ko + bf2);
            pb[5] = *reinterpret_cast<const float4*>(g_wt + (size_t)br2 * CDIM + ko + bf2 + 4);
        }

        // ---- MMAs: 4 k-steps, paired LDS.64 fragments ----
#pragma unroll
        for (int ks = 0; ks < 4; ks++) {
            const int kb = ks * 8 + 2 * ctg;
            uint32_t a[2][4];
#pragma unroll
            for (int mt = 0; mt < 2; mt++) {
                int row = wm * 32 + mt * 16;
                float2 f0 = *reinterpret_cast<const float2*>(&As[(row + g) * PJP + kb]);
                float2 f1 = *reinterpret_cast<const float2*>(&As[(row + g + 8) * PJP + kb]);
                a[mt][0] = __float_as_uint(f0.x); a[mt][1] = __float_as_uint(f1.x);
                a[mt][2] = __float_as_uint(f0.y); a[mt][3] = __float_as_uint(f1.y);
            }
#pragma unroll
            for (int nt = 0; nt < 6; nt++) {
                int n = wn * 48 + nt * 8;
                float2 bf = *reinterpret_cast<const float2*>(&Bs[(n + g) * PJP + kb]);
                uint32_t b[2];
                b[0] = __float_as_uint(bf.x); b[1] = __float_as_uint(bf.y);
                mma_tf32(acc[0][nt], a[0], b);
                mma_tf32(acc[1][nt], a[1], b);
            }
        }
        __syncthreads();
    }

    // ---- epilogue ----
    float* Vtr = sbuf;    // [64][68] reuse
#pragma unroll
    for (int mt = 0; mt < 2; mt++) {
#pragma unroll
        for (int nt = 0; nt < 6; nt++) {
            int col = wn * 48 + nt * 8 + 2 * ctg;
            int mat = col >> 6, c0 = col & 63;
            int r0 = row0 + wm * 32 + mt * 16 + g;
            if (mat < 2) {
                float* gp = (mat == 0) ? g_q : g_k;
                gp[(size_t)r0 * HDIM + perm8(c0)]           = tf32r(acc[mt][nt][0]);
                gp[(size_t)r0 * HDIM + perm8(c0 + 1)]       = tf32r(acc[mt][nt][1]);
                gp[(size_t)(r0 + 8) * HDIM + perm8(c0)]     = tf32r(acc[mt][nt][2]);
                gp[(size_t)(r0 + 8) * HDIM + perm8(c0 + 1)] = tf32r(acc[mt][nt][3]);
            } else {
                int tl = wm * 32 + mt * 16 + g;      // 0..55 (+8 below)
                Vtr[c0 * 68 + tl]           = tf32r(acc[mt][nt][0]);
                Vtr[(c0 + 1) * 68 + tl]     = tf32r(acc[mt][nt][1]);
                Vtr[c0 * 68 + tl + 8]       = tf32r(acc[mt][nt][2]);
                Vtr[(c0 + 1) * 68 + tl + 8] = tf32r(acc[mt][nt][3]);
            }
        }
    }
    __syncthreads();

    // coalesced V writes: 64 h-rows x 64 t (256B bursts)
    {
        const int b  = row0 >> 11;
        const int t0 = row0 & 2047;
#pragma unroll
        for (int i = 0; i < 4; i++) {
            int idx = t + 256 * i;
            int h = idx >> 4, c = (idx & 15) * 4;
            float4 v = *reinterpret_cast<const float4*>(&Vtr[h * 68 + c]);
            *reinterpret_cast<float4*>(
                &g_vt[((size_t)b * HDIM + h) * SEQ + t0 + c]) = v;
        }
    }
}

// ---------------------------------------------------------------------------
// Kernel 2: causal flash attention via tf32 mma.sync.
// CTA tile 128q; 64-col k-blocks, cp.async double-buffered.
// S C-frag feeds PV A-frag by register relabel (V stored unpermuted).
// Softmax in log2 domain (ex2.approx).
// smem: Qs[128][72] + 2x K[64][72] + 2x V[64][72] = 110,592 B -> 2 CTAs/SM.
// ---------------------------------------------------------------------------
#define QP 72
#define OFF_KB(buf) (128 * QP + (buf) * 64 * QP)
#define OFF_VB(buf) (128 * QP + 2 * 64 * QP + (buf) * 64 * QP)
#define ATTN_SMEM_FLOATS (128 * QP + 4 * 64 * QP)
#define ATTN_SMEM_BYTES (ATTN_SMEM_FLOATS * 4)

__global__ __launch_bounds__(256, 2) void attn_kernel(float* __restrict__ out)
{
    extern __shared__ float smf[];
    const uint32_t smb = smem_u32(smf);

    const int t    = threadIdx.x;
    const int wid  = t >> 5;
    const int lane = t & 31;
    const int g    = lane >> 2;
    const int ctg  = lane & 3;
    const int qw   = wid * 16;
    const int b    = blockIdx.y;
    const int qt   = (gridDim.x - 1) - blockIdx.x;   // heavy tiles first
    const int q0   = qt * 128;
    const int nk   = 2 * qt + 2;                     // 64-col k-blocks

    const float* kg0 = g_k  + ((size_t)b * SEQ) * HDIM;
    const float* vg0 = g_vt + ((size_t)b * HDIM) * SEQ;

    // stage Q (cp.async, pre-rounded & perm8'd on h)
    {
        const float* qg = g_q + ((size_t)b * SEQ + q0) * HDIM;
#pragma unroll
        for (int i = 0; i < 8; i++) {
            int idx = t + 256 * i;
            int r = idx >> 4, c = (idx & 15) * 4;
            cp16(smb + (uint32_t)(r * QP + c) * 4, qg + (size_t)r * HDIM + c);
        }
    }
    // stage K/V block 0 into buf 0
    {
#pragma unroll
        for (int i = 0; i < 4; i++) {
            int idx = t + 256 * i;
            int r = idx >> 4, c = (idx & 15) * 4;
            cp16(smb + (uint32_t)(OFF_KB(0) + r * QP + c) * 4,
                 kg0 + (size_t)r * HDIM + c);
            cp16(smb + (uint32_t)(OFF_VB(0) + r * QP + c) * 4,
                 vg0 + (size_t)r * SEQ + c);
        }
    }
    CP_COMMIT(); CP_WAIT0(); __syncthreads();

    float mrow[2] = { -CUDART_INF_F, -CUDART_INF_F };   // log2 domain
    float lrow[2] = { 0.f, 0.f };
    float o[8][4];
#pragma unroll
    for (int nt = 0; nt < 8; nt++)
#pragma unroll
        for (int i = 0; i < 4; i++) o[nt][i] = 0.f;

    for (int kt = 0; kt < nk; kt++) {
        const int cur = kt & 1;

        // prefetch next k-block into the other buffer
        if (kt + 1 < nk) {
            const float* kg = kg0 + (size_t)(kt + 1) * 64 * HDIM;
            const float* vg = vg0 + (size_t)(kt + 1) * 64;
#pragma unroll
            for (int i = 0; i < 4; i++) {
                int idx = t + 256 * i;
                int r = idx >> 4, c = (idx & 15) * 4;
                cp16(smb + (uint32_t)(OFF_KB(cur ^ 1) + r * QP + c) * 4,
                     kg + (size_t)r * HDIM + c);
                cp16(smb + (uint32_t)(OFF_VB(cur ^ 1) + r * QP + c) * 4,
                     vg + (size_t)r * SEQ + c);
            }
        }
        CP_COMMIT();

        const float* Kb = smf + OFF_KB(cur);
        const float* Vb = smf + OFF_VB(cur);

        // ---- S = Q K^T : warp tile 16 x 64 (paired LDS.64 fragments) ----
        float s[8][4];
#pragma unroll
        for (int nt = 0; nt < 8; nt++)
#pragma unroll
            for (int i = 0; i < 4; i++) s[nt][i] = 0.f;

#pragma unroll
        for (int ks = 0; ks < 8; ks++) {
            const int kb = ks * 8 + 2 * ctg;
            float2 qa0 = *reinterpret_cast<const float2*>(&smf[(qw + g) * QP + kb]);
            float2 qa1 = *reinterpret_cast<const float2*>(&smf[(qw + g + 8) * QP + kb]);
            uint32_t a[4];
            a[0] = __float_as_uint(qa0.x); a[1] = __float_as_uint(qa1.x);
            a[2] = __float_as_uint(qa0.y); a[3] = __float_as_uint(qa1.y);
#pragma unroll
            for (int nt = 0; nt < 8; nt++) {
                float2 kf = *reinterpret_cast<const float2*>(&Kb[(nt * 8 + g) * QP + kb]);
                uint32_t bb[2];
                bb[0] = __float_as_uint(kf.x); bb[1] = __float_as_uint(kf.y);
                mma_tf32(s[nt], a, bb);
            }
        }

        // ---- scale (log2 domain) + causal mask + online softmax ----
        const bool tail = (kt >= nk - 2);
        const int r0gl = q0 + qw + g, r1gl = r0gl + 8;
        const int kbase = kt * 64;
        float rm0 = -CUDART_INF_F, rm1 = -CUDART_INF_F;
#pragma unroll
        for (int nt = 0; nt < 8; nt++) {
            int cl = kbase + nt * 8 + 2 * ctg;
#pragma unroll
            for (int c = 0; c < 2; c++) {
                float v0 = s[nt][c] * SCL2;
                float v1 = s[nt][2 + c] * SCL2;
                if (tail) {
                    if (cl + c > r0gl) v0 = -1e30f;
                    if (cl + c > r1gl) v1 = -1e30f;
                }
                s[nt][c] = v0; s[nt][2 + c] = v1;
                rm0 = fmaxf(rm0, v0); rm1 = fmaxf(rm1, v1);
            }
        }
        rm0 = fmaxf(rm0, __shfl_xor_sync(0xffffffffu, rm0, 1));
        rm0 = fmaxf(rm0, __shfl_xor_sync(0xffffffffu, rm0, 2));
        rm1 = fmaxf(rm1, __shfl_xor_sync(0xffffffffu, rm1, 1));
        rm1 = fmaxf(rm1, __shfl_xor_sync(0xffffffffu, rm1, 2));

        float mn0 = fmaxf(mrow[0], rm0), mn1 = fmaxf(mrow[1], rm1);
        float fc0 = ex2(mrow[0] - mn0), fc1 = ex2(mrow[1] - mn1);
        float rs0 = 0.f, rs1 = 0.f;
#pragma unroll
        for (int nt = 0; nt < 8; nt++) {
#pragma unroll
            for (int c = 0; c < 2; c++) {
                float p0 = ex2(s[nt][c] - mn0);
                float p1 = ex2(s[nt][2 + c] - mn1);
                s[nt][c] = p0; s[nt][2 + c] = p1;
                rs0 += p0; rs1 += p1;
            }
        }
        rs0 += __shfl_xor_sync(0xffffffffu, rs0, 1);
        rs0 += __shfl_xor_sync(0xffffffffu, rs0, 2);
        rs1 += __shfl_xor_sync(0xffffffffu, rs1, 1);
        rs1 += __shfl_xor_sync(0xffffffffu, rs1, 2);

        lrow[0] = lrow[0] * fc0 + rs0;
        lrow[1] = lrow[1] * fc1 + rs1;
        mrow[0] = mn0; mrow[1] = mn1;
#pragma unroll
        for (int nt = 0; nt < 8; nt++) {
            o[nt][0] *= fc0; o[nt][1] *= fc0;
            o[nt][2] *= fc1; o[nt][3] *= fc1;
        }

        // ---- O += P V : S C-frag IS the A-frag (relabel {c0,c2,c1,c3});
        //      V physical row j == logical k j, so pairings line up. ----
#pragma unroll
        for (int ks = 0; ks < 8; ks++) {
            const int kb = ks * 8 + 2 * ctg;
            uint32_t a[4];
            a[0] = __float_as_uint(s[ks][0]);
            a[1] = __float_as_uint(s[ks][2]);
            a[2] = __float_as_uint(s[ks][1]);
            a[3] = __float_as_uint(s[ks][3]);
#pragma unroll
            for (int nt = 0; nt < 8; nt++) {
                float2 vf = *reinterpret_cast<const float2*>(&Vb[(nt * 8 + g) * QP + kb]);
                uint32_t bb[2];
                bb[0] = __float_as_uint(vf.x); bb[1] = __float_as_uint(vf.y);
                mma_tf32(o[nt], a, bb);
            }
        }

        CP_WAIT0();
        __syncthreads();
    }

    // ---- epilogue: normalize, end-token row mask, store ----
    const int limit = g_limit[b];
    const float qnan = __int_as_float(0x7FC00000);
    const int q0g = q0 + qw + g;
    const float inv0 = 1.f / lrow[0];
    const float inv1 = 1.f / lrow[1];
#pragma unroll
    for (int nt = 0; nt < 8; nt++) {
        int col = nt * 8 + 2 * ctg;
        float2 r0v, r1v;
        if (q0g >= limit) r0v = make_float2(qnan, qnan);
        else r0v = make_float2(o[nt][0] * inv0, o[nt][1] * inv0);
        if (q0g + 8 >= limit) r1v = make_float2(qnan, qnan);
        else r1v = make_float2(o[nt][2] * inv1, o[nt][3] * inv1);
        *reinterpret_cast<float2*>(&out[((size_t)b * SEQ + q0g) * HDIM + col]) = r0v;
        *reinterpret_cast<float2*>(&out[((size_t)b * SEQ + q0g + 8) * HDIM + col]) = r1v;
    }
}

// ---------------------------------------------------------------------------
extern "C" void kernel_launch(void* const* d_in, const int* in_sizes, int n_in,
                              void* d_out, int out_size)
{
    const float* x  = (const float*)d_in[0];
    const float* Wk = (const float*)d_in[1];
    const float* Wq = (const float*)d_in[2];
    const float* Wv = (const float*)d_in[3];
    const int*  idx = (const int*)d_in[4];
    float* out = (float*)d_out;

    (void)in_sizes; (void)n_in; (void)out_size;

    cudaFuncSetAttribute(attn_kernel,
                         cudaFuncAttributeMaxDynamicSharedMemorySize,
                         ATTN_SMEM_BYTES);

    prep_kernel<<<64, 256>>>(Wk, Wq, Wv, idx);
    proj_kernel<<<ROWS_TOTAL / 64, 256>>>(x);
    attn_kernel<<<dim3(SEQ / 128, BATCH), 256, ATTN_SMEM_BYTES>>>(out);
}

// round 11
// speedup vs baseline: 2.2404x; 1.3031x over previous
#include <cuda_runtime.h>
#include <cuda_bf16.h>
#include <math_constants.h>
#include <cstdint>

// Problem shape (fixed): B=16, T=2048, C=512, H=64
#define BATCH 16
#define SEQ   2048
#define CDIM  512
#define HDIM  64
#define END_TOKEN 32000

#define ROWS_TOTAL (BATCH * SEQ)          // 32768
#define SCALE 0.04419417382415922f        // 512^-0.5
#define SCL2  0.06377946286456401f        // SCALE * log2(e)

__device__ __forceinline__ float tf32r(float x) {
    float y; asm("cvt.rna.tf32.f32 %0,%1;" : "=f"(y) : "f"(x)); return y;
}
__device__ __forceinline__ float ex2(float x) {
    float y; asm("ex2.approx.f32 %0,%1;" : "=f"(y) : "f"(x)); return y;
}
__device__ __forceinline__ uint32_t smem_u32(const void* p) {
    uint32_t a;
    asm("{ .reg .u64 t; cvta.to.shared.u64 t, %1; cvt.u32.u64 %0, t; }"
        : "=r"(a) : "l"(p));
    return a;
}
__device__ __forceinline__ void cp16(uint32_t dst, const void* src) {
    asm volatile("cp.async.cg.shared.global [%0], [%1], 16;"
                 :: "r"(dst), "l"(src) : "memory");
}
#define CP_COMMIT() asm volatile("cp.async.commit_group;" ::: "memory")
#define CP_WAIT0()  asm volatile("cp.async.wait_group 0;" ::: "memory")

// pair-permutation within 8: logical i -> physical (puts (i, i+4) adjacent)
__device__ __forceinline__ int perm8(int i) {
    return (i & ~7) | ((i & 3) << 1) | ((i >> 2) & 1);
}

// m16n8k8 tf32 mma (sm_80 portable feature -> fallback HMMA on sm_103)
__device__ __forceinline__ void mma_tf32(float* d, const uint32_t* a, const uint32_t* b) {
    asm volatile(
        "mma.sync.aligned.m16n8k8.row.col.f32.tf32.tf32.f32 "
        "{%0,%1,%2,%3}, {%4,%5,%6,%7}, {%8,%9}, {%0,%1,%2,%3};"
        : "+f"(d[0]), "+f"(d[1]), "+f"(d[2]), "+f"(d[3])
        : "r"(a[0]), "r"(a[1]), "r"(a[2]), "r"(a[3]), "r"(b[0]), "r"(b[1]));
}

// Scratch (allocation-free rule: __device__ globals)
__device__ float g_q[ROWS_TOTAL * HDIM];
__device__ float g_k[ROWS_TOTAL * HDIM];
__device__ float g_vt[BATCH * HDIM * SEQ];
__device__ float g_wt[3 * HDIM * CDIM];   // W^T tf32: [mat][n][perm8(k)]
__device__ int   g_limit[BATCH];
// split-K partial results: 16 b x 8 heavy qt x 2 pieces
__device__ float g_po[BATCH * 8 * 2 * 128 * 64];   // unnormalized O
__device__ float g_pml[BATCH * 8 * 2 * 256];       // m[128] | l[128]

// Piece table (heavy-first). qt<8: single direct piece. qt>=8: two pieces.
__device__ const int PQT[24] = {7,8,9,10,11,12,13,14,15,15, 6,14, 5,13,
                                4,12, 3,11, 2,10, 1,9, 0,8};
__device__ const int PP1[24] = {0,0,0,0,0,0,0,0,0,1, 0,1, 0,1,
                                0,1, 0,1, 0,1, 0,1, 0,1};   // is piece1

// ---------------------------------------------------------------------------
// Kernel 0 (merged): blocks 0..47 transpose W (perm8 on k, tf32-rounded);
// blocks 48..63 run the end-token scan (faithful; never fires here).
// ---------------------------------------------------------------------------
__global__ void prep_kernel(const float* __restrict__ Wk,
                            const float* __restrict__ Wq,
                            const float* __restrict__ Wv,
                            const int* __restrict__ idx)
{
    if (blockIdx.x < 48) {
        const int m  = blockIdx.x / 16;
        const int ks = blockIdx.x % 16;           // k-slice of 32
        const float* src = (m == 0) ? Wq : (m == 1) ? Wk : Wv;
        float* dst = g_wt + (size_t)m * HDIM * CDIM;
        for (int i = threadIdx.x; i < 32 * 64; i += 256) {
            int k = ks * 32 + (i >> 6);
            int n = i & 63;
            dst[(size_t)n * CDIM + perm8(k)] = tf32r(src[(size_t)k * HDIM + n]);
        }
    } else {
        __shared__ int best;
        if (threadIdx.x == 0) best = SEQ;
        __syncthreads();
        const int b = blockIdx.x - 48;
        for (int t = threadIdx.x; t < SEQ; t += blockDim.x)
            if (idx[(size_t)b * SEQ + t] == END_TOKEN) atomicMin(&best, t);
        __syncthreads();
        if (threadIdx.x == 0) g_limit[b] = best;
    }
}

// ---------------------------------------------------------------------------
// Kernel 1: QKV projection via tf32 mma.sync (64 rows x 192 cols per CTA).
// (unchanged from R10 — validated)
// ---------------------------------------------------------------------------
#define PJP 40

__global__ __launch_bounds__(256) void proj_kernel(const float* __restrict__ x)
{
    __shared__ float sbuf[64 * PJP + 192 * PJP];
    float* As = sbuf;
    float* Bs = sbuf + 64 * PJP;

    const int t    = threadIdx.x;
    const int wid  = t >> 5;
    const int lane = t & 31;
    const int g    = lane >> 2;
    const int ctg  = lane & 3;
    const int wm   = wid >> 2;
    const int wn   = wid & 3;
    const int row0 = blockIdx.x * 64;

    const int ar = t >> 2, af = (t & 3) * 8;
    const int br0 = t >> 2,           bf0 = (t & 3) * 8;
    const int br1 = (t + 256) >> 2,   bf1 = ((t + 256) & 3) * 8;
    const int br2 = (t + 512) >> 2,   bf2 = ((t + 512) & 3) * 8;

    float acc[2][6][4];
#pragma unroll
    for (int mt = 0; mt < 2; mt++)
#pragma unroll
        for (int nt = 0; nt < 6; nt++)
#pragma unroll
            for (int i = 0; i < 4; i++) acc[mt][nt][i] = 0.f;

    float4 pa0, pa1, pb[6];
    {
        const float* xp = x + (size_t)(row0 + ar) * CDIM + af;
        pa0 = *reinterpret_cast<const float4*>(xp);
        pa1 = *reinterpret_cast<const float4*>(xp + 4);
        pb[0] = *reinterpret_cast<const float4*>(g_wt + (size_t)br0 * CDIM + bf0);
        pb[1] = *reinterpret_cast<const float4*>(g_wt + (size_t)br0 * CDIM + bf0 + 4);
        pb[2] = *reinterpret_cast<const float4*>(g_wt + (size_t)br1 * CDIM + bf1);
        pb[3] = *reinterpret_cast<const float4*>(g_wt + (size_t)br1 * CDIM + bf1 + 4);
        pb[4] = *reinterpret_cast<const float4*>(g_wt + (size_t)br2 * CDIM + bf2);
        pb[5] = *reinterpret_cast<const float4*>(g_wt + (size_t)br2 * CDIM + bf2 + 4);
    }

    for (int kc = 0; kc < 16; kc++) {
        {
            float* a = &As[ar * PJP + af];
            *reinterpret_cast<float2*>(&a[0]) = make_float2(tf32r(pa0.x), tf32r(pa1.x));
            *reinterpret_cast<float2*>(&a[2]) = make_float2(tf32r(pa0.y), tf32r(pa1.y));
            *reinterpret_cast<float2*>(&a[4]) = make_float2(tf32r(pa0.z), tf32r(pa1.z));
            *reinterpret_cast<float2*>(&a[6]) = make_float2(tf32r(pa0.w), tf32r(pa1.w));
            *reinterpret_cast<float4*>(&Bs[br0 * PJP + bf0])     = pb[0];
            *reinterpret_cast<float4*>(&Bs[br0 * PJP + bf0 + 4]) = pb[1];
            *reinterpret_cast<float4*>(&Bs[br1 * PJP + bf1])     = pb[2];
            *reinterpret_cast<float4*>(&Bs[br1 * PJP + bf1 + 4]) = pb[3];
            *reinterpret_cast<float4*>(&Bs[br2 * PJP + bf2])     = pb[4];
            *reinterpret_cast<float4*>(&Bs[br2 * PJP + bf2 + 4]) = pb[5];
        }
        __syncthreads();

        if (kc < 15) {
            const int ko = (kc + 1) * 32;
            const float* xp = x + (size_t)(row0 + ar) * CDIM + ko + af;
            pa0 = *reinterpret_cast<const float4*>(xp);
            pa1 = *reinterpret_cast<const float4*>(xp + 4);
            pb[0] = *reinterpret_cast<const float4*>(g_wt + (size_t)br0 * CDIM + ko + bf0);
            pb[1] = *reinterpret_cast<const float4*>(g_wt + (size_t)br0 * CDIM + ko + bf0 + 4);
            pb[2] = *reinterpret_cast<const float4*>(g_wt + (size_t)br1 * CDIM + ko + bf1);
            pb[3] = *reinterpret_cast<const float4*>(g_wt + (size_t)br1 * CDIM + ko + bf1 + 4);
            pb[4] = *reinterpret_cast<const float4*>(g_wt + (size_t)br2 * CDIM + ko + bf2);
            pb[5] = *reinterpret_cast<const float4*>(g_wt + (size_t)br2 * CDIM + ko + bf2 + 4);
        }

#pragma unroll
        for (int ks = 0; ks < 4; ks++) {
            const int kb = ks * 8 + 2 * ctg;
            uint32_t a[2][4];
#pragma unroll
            for (int mt = 0; mt < 2; mt++) {
                int row = wm * 32 + mt * 16;
                float2 f0 = *reinterpret_cast<const float2*>(&As[(row + g) * PJP + kb]);
                float2 f1 = *reinterpret_cast<const float2*>(&As[(row + g + 8) * PJP + kb]);
                a[mt][0] = __float_as_uint(f0.x); a[mt][1] = __float_as_uint(f1.x);
                a[mt][2] = __float_as_uint(f0.y); a[mt][3] = __float_as_uint(f1.y);
            }
#pragma unroll
            for (int nt = 0; nt < 6; nt++) {
                int n = wn * 48 + nt * 8;
                float2 bf = *reinterpret_cast<const float2*>(&Bs[(n + g) * PJP + kb]);
                uint32_t b[2];
                b[0] = __float_as_uint(bf.x); b[1] = __float_as_uint(bf.y);
                mma_tf32(acc[0][nt], a[0], b);
                mma_tf32(acc[1][nt], a[1], b);
            }
        }
        __syncthreads();
    }

    float* Vtr = sbuf;
#pragma unroll
    for (int mt = 0; mt < 2; mt++) {
#pragma unroll
        for (int nt = 0; nt < 6; nt++) {
            int col = wn * 48 + nt * 8 + 2 * ctg;
            int mat = col >> 6, c0 = col & 63;
            int r0 = row0 + wm * 32 + mt * 16 + g;
            if (mat < 2) {
                float* gp = (mat == 0) ? g_q : g_k;
                gp[(size_t)r0 * HDIM + perm8(c0)]           = tf32r(acc[mt][nt][0]);
                gp[(size_t)r0 * HDIM + perm8(c0 + 1)]       = tf32r(acc[mt][nt][1]);
                gp[(size_t)(r0 + 8) * HDIM + perm8(c0)]     = tf32r(acc[mt][nt][2]);
                gp[(size_t)(r0 + 8) * HDIM + perm8(c0 + 1)] = tf32r(acc[mt][nt][3]);
            } else {
                int tl = wm * 32 + mt * 16 + g;
                Vtr[c0 * 68 + tl]           = tf32r(acc[mt][nt][0]);
                Vtr[(c0 + 1) * 68 + tl]     = tf32r(acc[mt][nt][1]);
                Vtr[c0 * 68 + tl + 8]       = tf32r(acc[mt][nt][2]);
                Vtr[(c0 + 1) * 68 + tl + 8] = tf32r(acc[mt][nt][3]);
            }
        }
    }
    __syncthreads();

    {
        const int b  = row0 >> 11;
        const int t0 = row0 & 2047;
#pragma unroll
        for (int i = 0; i < 4; i++) {
            int idx = t + 256 * i;
            int h = idx >> 4, c = (idx & 15) * 4;
            float4 v = *reinterpret_cast<const float4*>(&Vtr[h * 68 + c]);
            *reinterpret_cast<float4*>(
                &g_vt[((size_t)b * HDIM + h) * SEQ + t0 + c]) = v;
        }
    }
}

// ---------------------------------------------------------------------------
// Kernel 2: causal flash attention, split-K pieces.
// blockIdx.x = batch, blockIdx.y = piece (heavy-first table).
// qt<8: direct. qt>=8: piece0 = kb64[0,16), piece1 = kb64[16, 2qt+2).
// ---------------------------------------------------------------------------
#define QP 72
#define OFF_KB(buf) (128 * QP + (buf) * 64 * QP)
#define OFF_VB(buf) (128 * QP + 2 * 64 * QP + (buf) * 64 * QP)
#define ATTN_SMEM_FLOATS (128 * QP + 4 * 64 * QP)
#define ATTN_SMEM_BYTES (ATTN_SMEM_FLOATS * 4)

__global__ __launch_bounds__(256, 2) void attn_kernel(float* __restrict__ out)
{
    extern __shared__ float smf[];
    const uint32_t smb = smem_u32(smf);

    const int t    = threadIdx.x;
    const int wid  = t >> 5;
    const int lane = t & 31;
    const int g    = lane >> 2;
    const int ctg  = lane & 3;
    const int qw   = wid * 16;
    const int b    = blockIdx.x;
    const int pc   = blockIdx.y;
    const int qt   = PQT[pc];
    const int p1   = PP1[pc];
    const bool split = (qt >= 8);
    const int ks   = p1 ? 16 : 0;
    const int ke   = (split && !p1) ? 16 : (2 * qt + 2);
    const int q0   = qt * 128;

    const float* kg0 = g_k  + ((size_t)b * SEQ) * HDIM;
    const float* vg0 = g_vt + ((size_t)b * HDIM) * SEQ;

    // stage Q
    {
        const float* qg = g_q + ((size_t)b * SEQ + q0) * HDIM;
#pragma unroll
        for (int i = 0; i < 8; i++) {
            int idx = t + 256 * i;
            int r = idx >> 4, c = (idx & 15) * 4;
            cp16(smb + (uint32_t)(r * QP + c) * 4, qg + (size_t)r * HDIM + c);
        }
    }
    // stage K/V block ks into buf 0
    {
        const float* kg = kg0 + (size_t)ks * 64 * HDIM;
        const float* vg = vg0 + (size_t)ks * 64;
#pragma unroll
        for (int i = 0; i < 4; i++) {
            int idx = t + 256 * i;
            int r = idx >> 4, c = (idx & 15) * 4;
            cp16(smb + (uint32_t)(OFF_KB(0) + r * QP + c) * 4,
                 kg + (size_t)r * HDIM + c);
            cp16(smb + (uint32_t)(OFF_VB(0) + r * QP + c) * 4,
                 vg + (size_t)r * SEQ + c);
        }
    }
    CP_COMMIT(); CP_WAIT0(); __syncthreads();

    float mrow[2] = { -CUDART_INF_F, -CUDART_INF_F };   // log2 domain
    float lrow[2] = { 0.f, 0.f };
    float o[8][4];
#pragma unroll
    for (int nt = 0; nt < 8; nt++)
#pragma unroll
        for (int i = 0; i < 4; i++) o[nt][i] = 0.f;

    for (int kt = ks; kt < ke; kt++) {
        const int cur = (kt - ks) & 1;

        if (kt + 1 < ke) {
            const float* kg = kg0 + (size_t)(kt + 1) * 64 * HDIM;
            const float* vg = vg0 + (size_t)(kt + 1) * 64;
#pragma unroll
            for (int i = 0; i < 4; i++) {
                int idx = t + 256 * i;
                int r = idx >> 4, c = (idx & 15) * 4;
                cp16(smb + (uint32_t)(OFF_KB(cur ^ 1) + r * QP + c) * 4,
                     kg + (size_t)r * HDIM + c);
                cp16(smb + (uint32_t)(OFF_VB(cur ^ 1) + r * QP + c) * 4,
                     vg + (size_t)r * SEQ + c);
            }
        }
        CP_COMMIT();

        const float* Kb = smf + OFF_KB(cur);
        const float* Vb = smf + OFF_VB(cur);

        // ---- S = Q K^T ----
        float s[8][4];
#pragma unroll
        for (int nt = 0; nt < 8; nt++)
#pragma unroll
            for (int i = 0; i < 4; i++) s[nt][i] = 0.f;

#pragma unroll
        for (int kss = 0; kss < 8; kss++) {
            const int kb = kss * 8 + 2 * ctg;
            float2 qa0 = *reinterpret_cast<const float2*>(&smf[(qw + g) * QP + kb]);
            float2 qa1 = *reinterpret_cast<const float2*>(&smf[(qw + g + 8) * QP + kb]);
            uint32_t a[4];
            a[0] = __float_as_uint(qa0.x); a[1] = __float_as_uint(qa1.x);
            a[2] = __float_as_uint(qa0.y); a[3] = __float_as_uint(qa1.y);
#pragma unroll
            for (int nt = 0; nt < 8; nt++) {
                float2 kf = *reinterpret_cast<const float2*>(&Kb[(nt * 8 + g) * QP + kb]);
                uint32_t bb[2];
                bb[0] = __float_as_uint(kf.x); bb[1] = __float_as_uint(kf.y);
                mma_tf32(s[nt], a, bb);
            }
        }

        // ---- scale + causal mask + online softmax ----
        const bool tail = (kt >= 2 * qt);
        const int r0gl = q0 + qw + g, r1gl = r0gl + 8;
        const int kbase = kt * 64;
        float rm0 = -CUDART_INF_F, rm1 = -CUDART_INF_F;
#pragma unroll
        for (int nt = 0; nt < 8; nt++) {
            int cl = kbase + nt * 8 + 2 * ctg;
#pragma unroll
            for (int c = 0; c < 2; c++) {
                float v0 = s[nt][c] * SCL2;
                float v1 = s[nt][2 + c] * SCL2;
                if (tail) {
                    if (cl + c > r0gl) v0 = -1e30f;
                    if (cl + c > r1gl) v1 = -1e30f;
                }
                s[nt][c] = v0; s[nt][2 + c] = v1;
                rm0 = fmaxf(rm0, v0); rm1 = fmaxf(rm1, v1);
            }
        }
        rm0 = fmaxf(rm0, __shfl_xor_sync(0xffffffffu, rm0, 1));
        rm0 = fmaxf(rm0, __shfl_xor_sync(0xffffffffu, rm0, 2));
        rm1 = fmaxf(rm1, __shfl_xor_sync(0xffffffffu, rm1, 1));
        rm1 = fmaxf(rm1, __shfl_xor_sync(0xffffffffu, rm1, 2));

        float mn0 = fmaxf(mrow[0], rm0), mn1 = fmaxf(mrow[1], rm1);
        float fc0 = ex2(mrow[0] - mn0), fc1 = ex2(mrow[1] - mn1);
        float rs0 = 0.f, rs1 = 0.f;
#pragma unroll
        for (int nt = 0; nt < 8; nt++) {
#pragma unroll
            for (int c = 0; c < 2; c++) {
                float p0 = ex2(s[nt][c] - mn0);
                float p1 = ex2(s[nt][2 + c] - mn1);
                s[nt][c] = p0; s[nt][2 + c] = p1;
                rs0 += p0; rs1 += p1;
            }
        }
        rs0 += __shfl_xor_sync(0xffffffffu, rs0, 1);
        rs0 += __shfl_xor_sync(0xffffffffu, rs0, 2);
        rs1 += __shfl_xor_sync(0xffffffffu, rs1, 1);
        rs1 += __shfl_xor_sync(0xffffffffu, rs1, 2);

        lrow[0] = lrow[0] * fc0 + rs0;
        lrow[1] = lrow[1] * fc1 + rs1;
        mrow[0] = mn0; mrow[1] = mn1;
#pragma unroll
        for (int nt = 0; nt < 8; nt++) {
            o[nt][0] *= fc0; o[nt][1] *= fc0;
            o[nt][2] *= fc1; o[nt][3] *= fc1;
        }

        // ---- O += P V (S C-frag relabeled as A-frag) ----
#pragma unroll
        for (int kss = 0; kss < 8; kss++) {
            const int kb = kss * 8 + 2 * ctg;
            uint32_t a[4];
            a[0] = __float_as_uint(s[kss][0]);
            a[1] = __float_as_uint(s[kss][2]);
            a[2] = __float_as_uint(s[kss][1]);
            a[3] = __float_as_uint(s[kss][3]);
#pragma unroll
            for (int nt = 0; nt < 8; nt++) {
                float2 vf = *reinterpret_cast<const float2*>(&Vb[(nt * 8 + g) * QP + kb]);
                uint32_t bb[2];
                bb[0] = __float_as_uint(vf.x); bb[1] = __float_as_uint(vf.y);
                mma_tf32(o[nt], a, bb);
            }
        }

        CP_WAIT0();
        __syncthreads();
    }

    // ---- epilogue ----
    if (!split) {
        const int limit = g_limit[b];
        const float qnan = __int_as_float(0x7FC00000);
        const int q0g = q0 + qw + g;
        const float inv0 = 1.f / lrow[0];
        const float inv1 = 1.f / lrow[1];
#pragma unroll
        for (int nt = 0; nt < 8; nt++) {
            int col = nt * 8 + 2 * ctg;
            float2 r0v, r1v;
            if (q0g >= limit) r0v = make_float2(qnan, qnan);
            else r0v = make_float2(o[nt][0] * inv0, o[nt][1] * inv0);
            if (q0g + 8 >= limit) r1v = make_float2(qnan, qnan);
            else r1v = make_float2(o[nt][2] * inv1, o[nt][3] * inv1);
            *reinterpret_cast<float2*>(&out[((size_t)b * SEQ + q0g) * HDIM + col]) = r0v;
            *reinterpret_cast<float2*>(&out[((size_t)b * SEQ + q0g + 8) * HDIM + col]) = r1v;
        }
    } else {
        const int slot = (b * 8 + (qt - 8)) * 2 + p1;
        float* po  = g_po  + (size_t)slot * 128 * 64;
        float* pml = g_pml + (size_t)slot * 256;
        const int r0l = qw + g, r1l = r0l + 8;
#pragma unroll
        for (int nt = 0; nt < 8; nt++) {
            int col = nt * 8 + 2 * ctg;
            *reinterpret_cast<float2*>(&po[r0l * 64 + col]) =
                make_float2(o[nt][0], o[nt][1]);
            *reinterpret_cast<float2*>(&po[r1l * 64 + col]) =
                make_float2(o[nt][2], o[nt][3]);
        }
        if (ctg == 0) {
            pml[r0l] = mrow[0]; pml[128 + r0l] = lrow[0];
            pml[r1l] = mrow[1]; pml[128 + r1l] = lrow[1];
        }
    }
}

// ---------------------------------------------------------------------------
// Kernel 3: combine split-K partials for qt 8..15.
// grid (8 qt, 16 b), 256 threads: thread = (row, half-of-64-cols).
// ---------------------------------------------------------------------------
__global__ __launch_bounds__(256) void combine_kernel(float* __restrict__ out)
{
    const int qti = blockIdx.x;          // 0..7 -> qt = qti+8
    const int b   = blockIdx.y;
    const int slot0 = (b * 8 + qti) * 2;
    const float* O0  = g_po  + (size_t)slot0 * 8192;
    const float* O1  = O0 + 8192;
    const float* ml0 = g_pml + (size_t)slot0 * 256;
    const float* ml1 = ml0 + 256;

    const int t = threadIdx.x;
    const int r = t >> 1;
    const int hc = (t & 1) * 32;

    const float m0 = ml0[r], l0 = ml0[128 + r];
    const float m1 = ml1[r], l1 = ml1[128 + r];
    const float mm = fmaxf(m0, m1);
    const float f0 = ex2(m0 - mm), f1 = ex2(m1 - mm);
    const float inv = 1.f / (l0 * f0 + l1 * f1);

    const int q = (qti + 8) * 128 + r;
    const int limit = g_limit[b];
    float* op = out + ((size_t)b * SEQ + q) * HDIM + hc;

    if (q >= limit) {
        const float qnan = __int_as_float(0x7FC00000);
        float4 nv = make_float4(qnan, qnan, qnan, qnan);
#pragma unroll
        for (int j = 0; j < 8; j++)
            *reinterpret_cast<float4*>(op + j * 4) = nv;
    } else {
#pragma unroll
        for (int j = 0; j < 8; j++) {
            float4 a = *reinterpret_cast<const float4*>(&O0[r * 64 + hc + j * 4]);
            float4 c = *reinterpret_cast<const float4*>(&O1[r * 64 + hc + j * 4]);
            float4 rv;
            rv.x = (a.x * f0 + c.x * f1) * inv;
            rv.y = (a.y * f0 + c.y * f1) * inv;
            rv.z = (a.z * f0 + c.z * f1) * inv;
            rv.w = (a.w * f0 + c.w * f1) * inv;
            *reinterpret_cast<float4*>(op + j * 4) = rv;
        }
    }
}

// ---------------------------------------------------------------------------
extern "C" void kernel_launch(void* const* d_in, const int* in_sizes, int n_in,
                              void* d_out, int out_size)
{
    const float* x  = (const float*)d_in[0];
    const float* Wk = (const float*)d_in[1];
    const float* Wq = (const float*)d_in[2];
    const float* Wv = (const float*)d_in[3];
    const int*  idx = (const int*)d_in[4];
    float* out = (float*)d_out;

    (void)in_sizes; (void)n_in; (void)out_size;

    cudaFuncSetAttribute(attn_kernel,
                         cudaFuncAttributeMaxDynamicSharedMemorySize,
                         ATTN_SMEM_BYTES);

    prep_kernel<<<64, 256>>>(Wk, Wq, Wv, idx);
    proj_kernel<<<ROWS_TOTAL / 64, 256>>>(x);
    attn_kernel<<<dim3(BATCH, 24), 256, ATTN_SMEM_BYTES>>>(out);
    combine_kernel<<<dim3(8, BATCH), 256>>>(out);
}

// round 12
// speedup vs baseline: 2.2967x; 1.0251x over previous
#include <cuda_runtime.h>
#include <cuda_bf16.h>
#include <math_constants.h>
#include <cstdint>

// Problem shape (fixed): B=16, T=2048, C=512, H=64
#define BATCH 16
#define SEQ   2048
#define CDIM  512
#define HDIM  64
#define END_TOKEN 32000

#define ROWS_TOTAL (BATCH * SEQ)          // 32768
#define SCALE 0.04419417382415922f        // 512^-0.5
#define SCL2  0.06377946286456401f        // SCALE * log2(e)

__device__ __forceinline__ float tf32r(float x) {
    float y; asm("cvt.rna.tf32.f32 %0,%1;" : "=f"(y) : "f"(x)); return y;
}
__device__ __forceinline__ float ex2(float x) {
    float y; asm("ex2.approx.f32 %0,%1;" : "=f"(y) : "f"(x)); return y;
}
__device__ __forceinline__ uint32_t smem_u32(const void* p) {
    uint32_t a;
    asm("{ .reg .u64 t; cvta.to.shared.u64 t, %1; cvt.u32.u64 %0, t; }"
        : "=r"(a) : "l"(p));
    return a;
}
__device__ __forceinline__ void cp16(uint32_t dst, const void* src) {
    asm volatile("cp.async.cg.shared.global [%0], [%1], 16;"
                 :: "r"(dst), "l"(src) : "memory");
}
#define CP_COMMIT() asm volatile("cp.async.commit_group;" ::: "memory")
#define CP_WAIT0()  asm volatile("cp.async.wait_group 0;" ::: "memory")

// pair-permutation within 8: logical i -> physical (puts (i, i+4) adjacent)
__device__ __forceinline__ int perm8(int i) {
    return (i & ~7) | ((i & 3) << 1) | ((i >> 2) & 1);
}

// m16n8k8 tf32 mma (sm_80 portable feature -> fallback HMMA on sm_103)
__device__ __forceinline__ void mma_tf32(float* d, const uint32_t* a, const uint32_t* b) {
    asm volatile(
        "mma.sync.aligned.m16n8k8.row.col.f32.tf32.tf32.f32 "
        "{%0,%1,%2,%3}, {%4,%5,%6,%7}, {%8,%9}, {%0,%1,%2,%3};"
        : "+f"(d[0]), "+f"(d[1]), "+f"(d[2]), "+f"(d[3])
        : "r"(a[0]), "r"(a[1]), "r"(a[2]), "r"(a[3]), "r"(b[0]), "r"(b[1]));
}

// Scratch (allocation-free rule: __device__ globals)
// g_q: [row][perm8(h)] tf32(q*SCL2).  g_k: [row][perm8(h)] tf32.
// g_vt: [b][h][phi16(t)] tf32 (t interleaved within 16-blocks for LDS.128).
__device__ float g_q[ROWS_TOTAL * HDIM];
__device__ float g_k[ROWS_TOTAL * HDIM];
__device__ float g_vt[BATCH * HDIM * SEQ];
__device__ float g_wt[3 * HDIM * CDIM];   // W^T tf32: [mat][n][perm8(k)]
__device__ int   g_limit[BATCH];
// split-K partial results: 16 b x 8 heavy qt x 2 pieces
__device__ float g_po[BATCH * 8 * 2 * 128 * 64];   // unnormalized O
__device__ float g_pml[BATCH * 8 * 2 * 256];       // m[128] | l[128]

// Piece table (heavy-first). qt<8: single direct piece. qt>=8: two pieces.
__device__ const int PQT[24] = {7,8,9,10,11,12,13,14,15,15, 6,14, 5,13,
                                4,12, 3,11, 2,10, 1,9, 0,8};
__device__ const int PP1[24] = {0,0,0,0,0,0,0,0,0,1, 0,1, 0,1,
                                0,1, 0,1, 0,1, 0,1, 0,1};   // is piece1

// ---------------------------------------------------------------------------
// Kernel 0 (merged): blocks 0..47 transpose W (perm8 on k, tf32-rounded);
// blocks 48..63 run the end-token scan (faithful; never fires here).
// ---------------------------------------------------------------------------
__global__ void prep_kernel(const float* __restrict__ Wk,
                            const float* __restrict__ Wq,
                            const float* __restrict__ Wv,
                            const int* __restrict__ idx)
{
    if (blockIdx.x < 48) {
        const int m  = blockIdx.x / 16;
        const int ks = blockIdx.x % 16;           // k-slice of 32
        const float* src = (m == 0) ? Wq : (m == 1) ? Wk : Wv;
        float* dst = g_wt + (size_t)m * HDIM * CDIM;
        for (int i = threadIdx.x; i < 32 * 64; i += 256) {
            int k = ks * 32 + (i >> 6);
            int n = i & 63;
            dst[(size_t)n * CDIM + perm8(k)] = tf32r(src[(size_t)k * HDIM + n]);
        }
    } else {
        __shared__ int best;
        if (threadIdx.x == 0) best = SEQ;
        __syncthreads();
        const int b = blockIdx.x - 48;
        for (int t = threadIdx.x; t < SEQ; t += blockDim.x)
            if (idx[(size_t)b * SEQ + t] == END_TOKEN) atomicMin(&best, t);
        __syncthreads();
        if (threadIdx.x == 0) g_limit[b] = best;
    }
}

// ---------------------------------------------------------------------------
// Kernel 1: QKV projection via tf32 mma.sync (64 rows x 192 cols per CTA).
// Epilogue: Q pre-scaled by SCL2; V t-interleaved (phi16) for LDS.128 reads.
// ---------------------------------------------------------------------------
#define PJP 40

__global__ __launch_bounds__(256) void proj_kernel(const float* __restrict__ x)
{
    __shared__ float sbuf[64 * PJP + 192 * PJP];
    float* As = sbuf;
    float* Bs = sbuf + 64 * PJP;

    const int t    = threadIdx.x;
    const int wid  = t >> 5;
    const int lane = t & 31;
    const int g    = lane >> 2;
    const int ctg  = lane & 3;
    const int wm   = wid >> 2;
    const int wn   = wid & 3;
    const int row0 = blockIdx.x * 64;

    const int ar = t >> 2, af = (t & 3) * 8;
    const int br0 = t >> 2,           bf0 = (t & 3) * 8;
    const int br1 = (t + 256) >> 2,   bf1 = ((t + 256) & 3) * 8;
    const int br2 = (t + 512) >> 2,   bf2 = ((t + 512) & 3) * 8;

    float acc[2][6][4];
#pragma unroll
    for (int mt = 0; mt < 2; mt++)
#pragma unroll
        for (int nt = 0; nt < 6; nt++)
#pragma unroll
            for (int i = 0; i < 4; i++) acc[mt][nt][i] = 0.f;

    float4 pa0, pa1, pb[6];
    {
        const float* xp = x + (size_t)(row0 + ar) * CDIM + af;
        pa0 = *reinterpret_cast<const float4*>(xp);
        pa1 = *reinterpret_cast<const float4*>(xp + 4);
        pb[0] = *reinterpret_cast<const float4*>(g_wt + (size_t)br0 * CDIM + bf0);
        pb[1] = *reinterpret_cast<const float4*>(g_wt + (size_t)br0 * CDIM + bf0 + 4);
        pb[2] = *reinterpret_cast<const float4*>(g_wt + (size_t)br1 * CDIM + bf1);
        pb[3] = *reinterpret_cast<const float4*>(g_wt + (size_t)br1 * CDIM + bf1 + 4);
        pb[4] = *reinterpret_cast<const float4*>(g_wt + (size_t)br2 * CDIM + bf2);
        pb[5] = *reinterpret_cast<const float4*>(g_wt + (size_t)br2 * CDIM + bf2 + 4);
    }

    for (int kc = 0; kc < 16; kc++) {
        {
            float* a = &As[ar * PJP + af];
            *reinterpret_cast<float2*>(&a[0]) = make_float2(tf32r(pa0.x), tf32r(pa1.x));
            *reinterpret_cast<float2*>(&a[2]) = make_float2(tf32r(pa0.y), tf32r(pa1.y));
            *reinterpret_cast<float2*>(&a[4]) = make_float2(tf32r(pa0.z), tf32r(pa1.z));
            *reinterpret_cast<float2*>(&a[6]) = make_float2(tf32r(pa0.w), tf32r(pa1.w));
            *reinterpret_cast<float4*>(&Bs[br0 * PJP + bf0])     = pb[0];
            *reinterpret_cast<float4*>(&Bs[br0 * PJP + bf0 + 4]) = pb[1];
            *reinterpret_cast<float4*>(&Bs[br1 * PJP + bf1])     = pb[2];
            *reinterpret_cast<float4*>(&Bs[br1 * PJP + bf1 + 4]) = pb[3];
            *reinterpret_cast<float4*>(&Bs[br2 * PJP + bf2])     = pb[4];
            *reinterpret_cast<float4*>(&Bs[br2 * PJP + bf2 + 4]) = pb[5];
        }
        __syncthreads();

        if (kc < 15) {
            const int ko = (kc + 1) * 32;
            const float* xp = x + (size_t)(row0 + ar) * CDIM + ko + af;
            pa0 = *reinterpret_cast<const float4*>(xp);
            pa1 = *reinterpret_cast<const float4*>(xp + 4);
            pb[0] = *reinterpret_cast<const float4*>(g_wt + (size_t)br0 * CDIM + ko + bf0);
            pb[1] = *reinterpret_cast<const float4*>(g_wt + (size_t)br0 * CDIM + ko + bf0 + 4);
            pb[2] = *reinterpret_cast<const float4*>(g_wt + (size_t)br1 * CDIM + ko + bf1);
            pb[3] = *reinterpret_cast<const float4*>(g_wt + (size_t)br1 * CDIM + ko + bf1 + 4);
            pb[4] = *reinterpret_cast<const float4*>(g_wt + (size_t)br2 * CDIM + ko + bf2);
            pb[5] = *reinterpret_cast<const float4*>(g_wt + (size_t)br2 * CDIM + ko + bf2 + 4);
        }

#pragma unroll
        for (int ks = 0; ks < 4; ks++) {
            const int kb = ks * 8 + 2 * ctg;
            uint32_t a[2][4];
#pragma unroll
            for (int mt = 0; mt < 2; mt++) {
                int row = wm * 32 + mt * 16;
                float2 f0 = *reinterpret_cast<const float2*>(&As[(row + g) * PJP + kb]);
                float2 f1 = *reinterpret_cast<const float2*>(&As[(row + g + 8) * PJP + kb]);
                a[mt][0] = __float_as_uint(f0.x); a[mt][1] = __float_as_uint(f1.x);
                a[mt][2] = __float_as_uint(f0.y); a[mt][3] = __float_as_uint(f1.y);
            }
#pragma unroll
            for (int nt = 0; nt < 6; nt++) {
                int n = wn * 48 + nt * 8;
                float2 bf = *reinterpret_cast<const float2*>(&Bs[(n + g) * PJP + kb]);
                uint32_t b[2];
                b[0] = __float_as_uint(bf.x); b[1] = __float_as_uint(bf.y);
                mma_tf32(acc[0][nt], a[0], b);
                mma_tf32(acc[1][nt], a[1], b);
            }
        }
        __syncthreads();
    }

    float* Vtr = sbuf;
#pragma unroll
    for (int mt = 0; mt < 2; mt++) {
#pragma unroll
        for (int nt = 0; nt < 6; nt++) {
            int col = wn * 48 + nt * 8 + 2 * ctg;
            int mat = col >> 6, c0 = col & 63;
            int r0 = row0 + wm * 32 + mt * 16 + g;
            if (mat == 0) {   // Q: pre-scale by SCL2, perm8 on h
                g_q[(size_t)r0 * HDIM + perm8(c0)]           = tf32r(acc[mt][nt][0] * SCL2);
                g_q[(size_t)r0 * HDIM + perm8(c0 + 1)]       = tf32r(acc[mt][nt][1] * SCL2);
                g_q[(size_t)(r0 + 8) * HDIM + perm8(c0)]     = tf32r(acc[mt][nt][2] * SCL2);
                g_q[(size_t)(r0 + 8) * HDIM + perm8(c0 + 1)] = tf32r(acc[mt][nt][3] * SCL2);
            } else if (mat == 1) {   // K: perm8 on h
                g_k[(size_t)r0 * HDIM + perm8(c0)]           = tf32r(acc[mt][nt][0]);
                g_k[(size_t)r0 * HDIM + perm8(c0 + 1)]       = tf32r(acc[mt][nt][1]);
                g_k[(size_t)(r0 + 8) * HDIM + perm8(c0)]     = tf32r(acc[mt][nt][2]);
                g_k[(size_t)(r0 + 8) * HDIM + perm8(c0 + 1)] = tf32r(acc[mt][nt][3]);
            } else {   // V: phi16 interleave on t (s-bit packs ks-pairs adjacently)
                int tl  = wm * 32 + mt * 16 + g;       // s-bit of tl is 0 here
                int tlp = (tl & ~15) + 4 * (g >> 1) + (g & 1);   // phi16(tl)
                Vtr[c0 * 68 + tlp]             = tf32r(acc[mt][nt][0]);
                Vtr[(c0 + 1) * 68 + tlp]       = tf32r(acc[mt][nt][1]);
                Vtr[c0 * 68 + tlp + 2]         = tf32r(acc[mt][nt][2]);  // phi16(tl+8)
                Vtr[(c0 + 1) * 68 + tlp + 2]   = tf32r(acc[mt][nt][3]);
            }
        }
    }
    __syncthreads();

    {
        const int b  = row0 >> 11;
        const int t0 = row0 & 2047;
#pragma unroll
        for (int i = 0; i < 4; i++) {
            int idx = t + 256 * i;
            int h = idx >> 4, c = (idx & 15) * 4;
            float4 v = *reinterpret_cast<const float4*>(&Vtr[h * 68 + c]);
            *reinterpret_cast<float4*>(
                &g_vt[((size_t)b * HDIM + h) * SEQ + t0 + c]) = v;
        }
    }
}

// ---------------------------------------------------------------------------
// Kernel 2: causal flash attention, split-K pieces.
// V fragments via LDS.128 (phi16 layout, stride 80 -> conflict-free).
// Q pre-scaled by SCL2 (softmax directly in log2 domain).
// smem: Q[128][72] + 2x K[64][72] + 2x V[64][80] = 114,688 B -> 2 CTAs/SM.
// ---------------------------------------------------------------------------
#define QP 72
#define VP 80
#define OFF_KB(buf) (128 * QP + (buf) * 64 * QP)
#define OFF_VB(buf) (128 * QP + 2 * 64 * QP + (buf) * 64 * VP)
#define ATTN_SMEM_FLOATS (128 * QP + 2 * 64 * QP + 2 * 64 * VP)
#define ATTN_SMEM_BYTES (ATTN_SMEM_FLOATS * 4)

__global__ __launch_bounds__(256, 2) void attn_kernel(float* __restrict__ out)
{
    extern __shared__ float smf[];
    const uint32_t smb = smem_u32(smf);

    const int t    = threadIdx.x;
    const int wid  = t >> 5;
    const int lane = t & 31;
    const int g    = lane >> 2;
    const int ctg  = lane & 3;
    const int qw   = wid * 16;
    const int b    = blockIdx.x;
    const int pc   = blockIdx.y;
    const int qt   = PQT[pc];
    const int p1   = PP1[pc];
    const bool split = (qt >= 8);
    const int ks   = p1 ? 16 : 0;
    const int ke   = (split && !p1) ? 16 : (2 * qt + 2);
    const int q0   = qt * 128;

    const float* kg0 = g_k  + ((size_t)b * SEQ) * HDIM;
    const float* vg0 = g_vt + ((size_t)b * HDIM) * SEQ;

    // stage Q
    {
        const float* qg = g_q + ((size_t)b * SEQ + q0) * HDIM;
#pragma unroll
        for (int i = 0; i < 8; i++) {
            int idx = t + 256 * i;
            int r = idx >> 4, c = (idx & 15) * 4;
            cp16(smb + (uint32_t)(r * QP + c) * 4, qg + (size_t)r * HDIM + c);
        }
    }
    // stage K/V block ks into buf 0
    {
        const float* kg = kg0 + (size_t)ks * 64 * HDIM;
        const float* vg = vg0 + (size_t)ks * 64;
#pragma unroll
        for (int i = 0; i < 4; i++) {
            int idx = t + 256 * i;
            int r = idx >> 4, c = (idx & 15) * 4;
            cp16(smb + (uint32_t)(OFF_KB(0) + r * QP + c) * 4,
                 kg + (size_t)r * HDIM + c);
            cp16(smb + (uint32_t)(OFF_VB(0) + r * VP + c) * 4,
                 vg + (size_t)r * SEQ + c);
        }
    }
    CP_COMMIT(); CP_WAIT0(); __syncthreads();

    float mrow[2] = { -CUDART_INF_F, -CUDART_INF_F };   // log2 domain
    float lrow[2] = { 0.f, 0.f };
    float o[8][4];
#pragma unroll
    for (int nt = 0; nt < 8; nt++)
#pragma unroll
        for (int i = 0; i < 4; i++) o[nt][i] = 0.f;

    for (int kt = ks; kt < ke; kt++) {
        const int cur = (kt - ks) & 1;

        if (kt + 1 < ke) {
            const float* kg = kg0 + (size_t)(kt + 1) * 64 * HDIM;
            const float* vg = vg0 + (size_t)(kt + 1) * 64;
#pragma unroll
            for (int i = 0; i < 4; i++) {
                int idx = t + 256 * i;
                int r = idx >> 4, c = (idx & 15) * 4;
                cp16(smb + (uint32_t)(OFF_KB(cur ^ 1) + r * QP + c) * 4,
                     kg + (size_t)r * HDIM + c);
                cp16(smb + (uint32_t)(OFF_VB(cur ^ 1) + r * VP + c) * 4,
                     vg + (size_t)r * SEQ + c);
            }
        }
        CP_COMMIT();

        const float* Kb = smf + OFF_KB(cur);
        const float* Vb = smf + OFF_VB(cur);

        // ---- S = Q K^T (Q pre-scaled) ----
        float s[8][4];
#pragma unroll
        for (int nt = 0; nt < 8; nt++)
#pragma unroll
            for (int i = 0; i < 4; i++) s[nt][i] = 0.f;

#pragma unroll
        for (int kss = 0; kss < 8; kss++) {
            const int kb = kss * 8 + 2 * ctg;
            float2 qa0 = *reinterpret_cast<const float2*>(&smf[(qw + g) * QP + kb]);
            float2 qa1 = *reinterpret_cast<const float2*>(&smf[(qw + g + 8) * QP + kb]);
            uint32_t a[4];
            a[0] = __float_as_uint(qa0.x); a[1] = __float_as_uint(qa1.x);
            a[2] = __float_as_uint(qa0.y); a[3] = __float_as_uint(qa1.y);
#pragma unroll
            for (int nt = 0; nt < 8; nt++) {
                float2 kf = *reinterpret_cast<const float2*>(&Kb[(nt * 8 + g) * QP + kb]);
                uint32_t bb[2];
                bb[0] = __float_as_uint(kf.x); bb[1] = __float_as_uint(kf.y);
                mma_tf32(s[nt], a, bb);
            }
        }

        // ---- causal mask + online softmax (log2 domain; S pre-scaled) ----
        const bool tail = (kt >= 2 * qt);
        const int r0gl = q0 + qw + g, r1gl = r0gl + 8;
        const int kbase = kt * 64;
        float rm0 = -CUDART_INF_F, rm1 = -CUDART_INF_F;
#pragma unroll
        for (int nt = 0; nt < 8; nt++) {
            int cl = kbase + nt * 8 + 2 * ctg;
#pragma unroll
            for (int c = 0; c < 2; c++) {
                float v0 = s[nt][c];
                float v1 = s[nt][2 + c];
                if (tail) {
                    if (cl + c > r0gl) v0 = -1e30f;
                    if (cl + c > r1gl) v1 = -1e30f;
                }
                s[nt][c] = v0; s[nt][2 + c] = v1;
                rm0 = fmaxf(rm0, v0); rm1 = fmaxf(rm1, v1);
            }
        }
        rm0 = fmaxf(rm0, __shfl_xor_sync(0xffffffffu, rm0, 1));
        rm0 = fmaxf(rm0, __shfl_xor_sync(0xffffffffu, rm0, 2));
        rm1 = fmaxf(rm1, __shfl_xor_sync(0xffffffffu, rm1, 1));
        rm1 = fmaxf(rm1, __shfl_xor_sync(0xffffffffu, rm1, 2));

        float mn0 = fmaxf(mrow[0], rm0), mn1 = fmaxf(mrow[1], rm1);
        float fc0 = ex2(mrow[0] - mn0), fc1 = ex2(mrow[1] - mn1);
        float rs0 = 0.f, rs1 = 0.f;
#pragma unroll
        for (int nt = 0; nt < 8; nt++) {
#pragma unroll
            for (int c = 0; c < 2; c++) {
                float p0 = ex2(s[nt][c] - mn0);
                float p1 = ex2(s[nt][2 + c] - mn1);
                s[nt][c] = p0; s[nt][2 + c] = p1;
                rs0 += p0; rs1 += p1;
            }
        }
        rs0 += __shfl_xor_sync(0xffffffffu, rs0, 1);
        rs0 += __shfl_xor_sync(0xffffffffu, rs0, 2);
        rs1 += __shfl_xor_sync(0xffffffffu, rs1, 1);
        rs1 += __shfl_xor_sync(0xffffffffu, rs1, 2);

        lrow[0] = lrow[0] * fc0 + rs0;
        lrow[1] = lrow[1] * fc1 + rs1;
        mrow[0] = mn0; mrow[1] = mn1;
#pragma unroll
        for (int nt = 0; nt < 8; nt++) {
            o[nt][0] *= fc0; o[nt][1] *= fc0;
            o[nt][2] *= fc1; o[nt][3] *= fc1;
        }

        // ---- O += P V : LDS.128 V fragments serve ks-pairs (phi16 layout) ----
#pragma unroll
        for (int u = 0; u < 4; u++) {
            uint32_t a0[4], a1[4];
            a0[0] = __float_as_uint(s[2*u][0]);
            a0[1] = __float_as_uint(s[2*u][2]);
            a0[2] = __float_as_uint(s[2*u][1]);
            a0[3] = __float_as_uint(s[2*u][3]);
            a1[0] = __float_as_uint(s[2*u+1][0]);
            a1[1] = __float_as_uint(s[2*u+1][2]);
            a1[2] = __float_as_uint(s[2*u+1][1]);
            a1[3] = __float_as_uint(s[2*u+1][3]);
            const int kb = 16 * u + 4 * ctg;
#pragma unroll
            for (int nt = 0; nt < 8; nt++) {
                float4 vf = *reinterpret_cast<const float4*>(&Vb[(nt * 8 + g) * VP + kb]);
                uint32_t b0[2], b1[2];
                b0[0] = __float_as_uint(vf.x); b0[1] = __float_as_uint(vf.y);
                b1[0] = __float_as_uint(vf.z); b1[1] = __float_as_uint(vf.w);
                mma_tf32(o[nt], a0, b0);
                mma_tf32(o[nt], a1, b1);
            }
        }

        CP_WAIT0();
        __syncthreads();
    }

    // ---- epilogue ----
    if (!split) {
        const int limit = g_limit[b];
        const float qnan = __int_as_float(0x7FC00000);
        const int q0g = q0 + qw + g;
        const float inv0 = 1.f / lrow[0];
        const float inv1 = 1.f / lrow[1];
#pragma unroll
        for (int nt = 0; nt < 8; nt++) {
            int col = nt * 8 + 2 * ctg;
            float2 r0v, r1v;
            if (q0g >= limit) r0v = make_float2(qnan, qnan);
            else r0v = make_float2(o[nt][0] * inv0, o[nt][1] * inv0);
            if (q0g + 8 >= limit) r1v = make_float2(qnan, qnan);
            else r1v = make_float2(o[nt][2] * inv1, o[nt][3] * inv1);
            *reinterpret_cast<float2*>(&out[((size_t)b * SEQ + q0g) * HDIM + col]) = r0v;
            *reinterpret_cast<float2*>(&out[((size_t)b * SEQ + q0g + 8) * HDIM + col]) = r1v;
        }
    } else {
        const int slot = (b * 8 + (qt - 8)) * 2 + p1;
        float* po  = g_po  + (size_t)slot * 128 * 64;
        float* pml = g_pml + (size_t)slot * 256;
        const int r0l = qw + g, r1l = r0l + 8;
#pragma unroll
        for (int nt = 0; nt < 8; nt++) {
            int col = nt * 8 + 2 * ctg;
            *reinterpret_cast<float2*>(&po[r0l * 64 + col]) =
                make_float2(o[nt][0], o[nt][1]);
            *reinterpret_cast<float2*>(&po[r1l * 64 + col]) =
                make_float2(o[nt][2], o[nt][3]);
        }
        if (ctg == 0) {
            pml[r0l] = mrow[0]; pml[128 + r0l] = lrow[0];
            pml[r1l] = mrow[1]; pml[128 + r1l] = lrow[1];
        }
    }
}

// ---------------------------------------------------------------------------
// Kernel 3: combine split-K partials for qt 8..15.
// ---------------------------------------------------------------------------
__global__ __launch_bounds__(256) void combine_kernel(float* __restrict__ out)
{
    const int qti = blockIdx.x;          // 0..7 -> qt = qti+8
    const int b   = blockIdx.y;
    const int slot0 = (b * 8 + qti) * 2;
    const float* O0  = g_po  + (size_t)slot0 * 8192;
    const float* O1  = O0 + 8192;
    const float* ml0 = g_pml + (size_t)slot0 * 256;
    const float* ml1 = ml0 + 256;

    const int t = threadIdx.x;
    const int r = t >> 1;
    const int hc = (t & 1) * 32;

    const float m0 = ml0[r], l0 = ml0[128 + r];
    const float m1 = ml1[r], l1 = ml1[128 + r];
    const float mm = fmaxf(m0, m1);
    const float f0 = ex2(m0 - mm), f1 = ex2(m1 - mm);
    const float inv = 1.f / (l0 * f0 + l1 * f1);

    const int q = (qti + 8) * 128 + r;
    const int limit = g_limit[b];
    float* op = out + ((size_t)b * SEQ + q) * HDIM + hc;

    if (q >= limit) {
        const float qnan = __int_as_float(0x7FC00000);
        float4 nv = make_float4(qnan, qnan, qnan, qnan);
#pragma unroll
        for (int j = 0; j < 8; j++)
            *reinterpret_cast<float4*>(op + j * 4) = nv;
    } else {
#pragma unroll
        for (int j = 0; j < 8; j++) {
            float4 a = *reinterpret_cast<const float4*>(&O0[r * 64 + hc + j * 4]);
            float4 c = *reinterpret_cast<const float4*>(&O1[r * 64 + hc + j * 4]);
            float4 rv;
            rv.x = (a.x * f0 + c.x * f1) * inv;
            rv.y = (a.y * f0 + c.y * f1) * inv;
            rv.z = (a.z * f0 + c.z * f1) * inv;
            rv.w = (a.w * f0 + c.w * f1) * inv;
            *reinterpret_cast<float4*>(op + j * 4) = rv;
        }
    }
}

// ---------------------------------------------------------------------------
extern "C" void kernel_launch(void* const* d_in, const int* in_sizes, int n_in,
                              void* d_out, int out_size)
{
    const float* x  = (const float*)d_in[0];
    const float* Wk = (const float*)d_in[1];
    const float* Wq = (const float*)d_in[2];
    const float* Wv = (const float*)d_in[3];
    const int*  idx = (const int*)d_in[4];
    float* out = (float*)d_out;

    (void)in_sizes; (void)n_in; (void)out_size;

    cudaFuncSetAttribute(attn_kernel,
                         cudaFuncAttributeMaxDynamicSharedMemorySize,
                         ATTN_SMEM_BYTES);

    prep_kernel<<<64, 256>>>(Wk, Wq, Wv, idx);
    proj_kernel<<<ROWS_TOTAL / 64, 256>>>(x);
    attn_kernel<<<dim3(BATCH, 24), 256, ATTN_SMEM_BYTES>>>(out);
    combine_kernel<<<dim3(8, BATCH), 256>>>(out);
}